// round 3
// baseline (speedup 1.0000x reference)
#include <cuda_runtime.h>
#include <math.h>

// Problem constants
#define BATCH 16
#define SEQ   1024          // H*W = 32*32
#define DM    512           // d_model
#define KD    128           // key dim
#define TEMP_F 30.0f
#define EPB   (SEQ*DM)      // elements per batch = 524288
#define NORM_SCALE_F 0.011048543456039806f   // sqrt(1/(512*16))

// ---------------- scratch (static device memory; allocation-free) ----------
__device__ __align__(16) float g_X  [BATCH*SEQ*DM];   // current x  (33.5 MB)
__device__ __align__(16) float g_mem[BATCH*SEQ*DM];   // encoder memory
__device__ __align__(16) float g_V2 [BATCH*SEQ*DM];   // memory * label
__device__ __align__(16) float g_T1 [BATCH*SEQ*DM];   // temp (attn out / t4)
__device__ __align__(16) float g_T2 [BATCH*SEQ*DM];   // temp (t2)
__device__ __align__(16) float g_W  [BATCH*SEQ*KD];   // wq/wk (8 MB)
__device__ __align__(16) float g_Wkm[BATCH*SEQ*KD];   // wk of memory (cross)
__device__ __align__(16) float g_Sc [BATCH*SEQ*SEQ];  // scores/aff (67 MB)
__device__ float g_mask[BATCH*SEQ];
__device__ float g_part[BATCH*256];
__device__ float g_ssf [BATCH];

// ---------------- batched SGEMM: C = A @ B (or A @ B^T) --------------------
// A: [M,K] row-major, B: [K,N] row-major (TRANSB=false) or [N,K] (TRANSB=true)
// 128x128 block tile, BK=8, 8x8 per thread, 256 threads. All dims divide evenly
// for every call site (M=1024; N in {128,512,1024}; K in {128,512,1024}).
template<bool TRANSB>
__global__ void __launch_bounds__(256)
k_sgemm(const float* __restrict__ Ag, const float* __restrict__ Bg,
        float* __restrict__ Cg, int M, int N, int K,
        size_t sA, size_t sB, size_t sC)
{
    constexpr int BK = 8;
    __shared__ float As[BK][128];
    __shared__ float Bs[BK][128];

    const float* A = Ag + (size_t)blockIdx.z * sA;
    const float* B = Bg + (size_t)blockIdx.z * sB;
    float*       C = Cg + (size_t)blockIdx.z * sC;

    const int bm = blockIdx.y * 128;
    const int bn = blockIdx.x * 128;
    const int tid = threadIdx.x;
    const int tx = tid & 15;        // 0..15 -> N
    const int ty = tid >> 4;        // 0..15 -> M
    const int arow = tid >> 1;      // 0..127
    const int acol = (tid & 1) * 4; // 0 or 4
    const int brow = tid >> 5;      // 0..7
    const int bcol = (tid & 31) * 4;

    float acc[8][8] = {};

    for (int k0 = 0; k0 < K; k0 += BK) {
        float4 av = *(const float4*)(A + (size_t)(bm + arow) * K + k0 + acol);
        As[acol+0][arow] = av.x; As[acol+1][arow] = av.y;
        As[acol+2][arow] = av.z; As[acol+3][arow] = av.w;
        if (TRANSB) {
            float4 bv = *(const float4*)(B + (size_t)(bn + arow) * K + k0 + acol);
            Bs[acol+0][arow] = bv.x; Bs[acol+1][arow] = bv.y;
            Bs[acol+2][arow] = bv.z; Bs[acol+3][arow] = bv.w;
        } else {
            *(float4*)&Bs[brow][bcol] =
                *(const float4*)(B + (size_t)(k0 + brow) * N + bn + bcol);
        }
        __syncthreads();
        #pragma unroll
        for (int kk = 0; kk < BK; kk++) {
            float ra[8], rb[8];
            #pragma unroll
            for (int i = 0; i < 8; i++) ra[i] = As[kk][ty*8 + i];
            #pragma unroll
            for (int j = 0; j < 8; j++) rb[j] = Bs[kk][tx*8 + j];
            #pragma unroll
            for (int i = 0; i < 8; i++)
                #pragma unroll
                for (int j = 0; j < 8; j++)
                    acc[i][j] = fmaf(ra[i], rb[j], acc[i][j]);
        }
        __syncthreads();
    }
    #pragma unroll
    for (int i = 0; i < 8; i++) {
        size_t off = (size_t)(bm + ty*8 + i) * N + bn + tx*8;
        *(float4*)(C + off)     = make_float4(acc[i][0], acc[i][1], acc[i][2], acc[i][3]);
        *(float4*)(C + off + 4) = make_float4(acc[i][4], acc[i][5], acc[i][6], acc[i][7]);
    }
}

// ---------------- transposes: [B,D,S] <-> [B,S,D] ---------------------------
__global__ void k_trans_in(const float* __restrict__ in, float* __restrict__ X)
{
    __shared__ float tile[32][33];
    int b = blockIdx.z;
    int d0 = blockIdx.y * 32, s0 = blockIdx.x * 32;
    for (int r = threadIdx.y; r < 32; r += 8)
        tile[r][threadIdx.x] = in[((size_t)b*DM + d0 + r) * SEQ + s0 + threadIdx.x];
    __syncthreads();
    for (int r = threadIdx.y; r < 32; r += 8)
        X[((size_t)b*SEQ + s0 + r) * DM + d0 + threadIdx.x] = tile[threadIdx.x][r];
}

__global__ void k_trans_out(const float* __restrict__ X, float* __restrict__ out)
{
    __shared__ float tile[32][33];
    int b = blockIdx.z;
    int d0 = blockIdx.y * 32, s0 = blockIdx.x * 32;
    for (int r = threadIdx.y; r < 32; r += 8)
        tile[r][threadIdx.x] = X[((size_t)b*SEQ + s0 + r) * DM + d0 + threadIdx.x];
    __syncthreads();
    for (int r = threadIdx.y; r < 32; r += 8)
        out[((size_t)b*DM + d0 + r) * SEQ + s0 + threadIdx.x] = tile[threadIdx.x][r];
}

// ---------------- bias add + row L2 normalize on [B,S,KD] ------------------
__global__ void k_bias_l2(float* __restrict__ W, const float* __restrict__ bias)
{
    int b = blockIdx.y, s = blockIdx.x, t = threadIdx.x;   // 128 threads
    size_t idx = ((size_t)b*SEQ + s) * KD + t;
    float v = W[idx] + bias[t];
    float sq = v * v;
    #pragma unroll
    for (int o = 16; o; o >>= 1) sq += __shfl_xor_sync(0xffffffffu, sq, o);
    __shared__ float sh[4];
    if ((t & 31) == 0) sh[t >> 5] = sq;
    __syncthreads();
    float tot = sh[0] + sh[1] + sh[2] + sh[3];
    W[idx] = v / fmaxf(sqrtf(tot), 1e-12f);
}

// ---------------- row softmax with temperature on [B,S,S] ------------------
__global__ void k_softmax(float* __restrict__ Sc)
{
    __shared__ float sh1[8], sh2[8];
    int b = blockIdx.y, q = blockIdx.x, t = threadIdx.x;   // 256 threads
    float* row = Sc + ((size_t)b*SEQ + q) * SEQ;
    float v0 = row[t]        * TEMP_F;
    float v1 = row[t + 256]  * TEMP_F;
    float v2 = row[t + 512]  * TEMP_F;
    float v3 = row[t + 768]  * TEMP_F;
    float m = fmaxf(fmaxf(v0, v1), fmaxf(v2, v3));
    #pragma unroll
    for (int o = 16; o; o >>= 1) m = fmaxf(m, __shfl_xor_sync(0xffffffffu, m, o));
    if ((t & 31) == 0) sh1[t >> 5] = m;
    __syncthreads();
    m = fmaxf(fmaxf(fmaxf(sh1[0], sh1[1]), fmaxf(sh1[2], sh1[3])),
              fmaxf(fmaxf(sh1[4], sh1[5]), fmaxf(sh1[6], sh1[7])));
    v0 = __expf(v0 - m); v1 = __expf(v1 - m);
    v2 = __expf(v2 - m); v3 = __expf(v3 - m);
    float sum = v0 + v1 + v2 + v3;
    #pragma unroll
    for (int o = 16; o; o >>= 1) sum += __shfl_xor_sync(0xffffffffu, sum, o);
    if ((t & 31) == 0) sh2[t >> 5] = sum;
    __syncthreads();
    sum = sh2[0]+sh2[1]+sh2[2]+sh2[3]+sh2[4]+sh2[5]+sh2[6]+sh2[7];
    float inv = 1.f / sum;
    row[t]       = v0 * inv;
    row[t + 256] = v1 * inv;
    row[t + 512] = v2 * inv;
    row[t + 768] = v3 * inv;
}

// ---------------- mask GEMV: mask[b,q] = aff[b,q,:] . label[b,:] ------------
__global__ void k_mask_gemv(const float* __restrict__ Sc, const float* __restrict__ lbl,
                            float* __restrict__ mask)
{
    __shared__ float sh[8];
    int b = blockIdx.y, q = blockIdx.x, t = threadIdx.x;
    const float* row = Sc + ((size_t)b*SEQ + q) * SEQ;
    const float* L = lbl + (size_t)b*SEQ;
    float s = 0.f;
    #pragma unroll
    for (int i = 0; i < 4; i++) { int j = t + 256*i; s += row[j] * L[j]; }
    #pragma unroll
    for (int o = 16; o; o >>= 1) s += __shfl_xor_sync(0xffffffffu, s, o);
    if ((t & 31) == 0) sh[t >> 5] = s;
    __syncthreads();
    if (t == 0) {
        float tot = sh[0]+sh[1]+sh[2]+sh[3]+sh[4]+sh[5]+sh[6]+sh[7];
        mask[b*SEQ + q] = tot;
    }
}

// ---------------- elementwise + deterministic sumsq partials ---------------
__global__ void k_ew_add_red(const float* __restrict__ a, const float* __restrict__ c,
                             float* __restrict__ y, float* __restrict__ part)
{
    int b = blockIdx.y;
    size_t base = (size_t)b*EPB + (size_t)blockIdx.x*2048;
    float sq = 0.f;
    #pragma unroll
    for (int r = 0; r < 8; r++) {
        size_t i = base + r*256 + threadIdx.x;
        float v = a[i] + c[i];
        y[i] = v; sq += v * v;
    }
    __shared__ float sh[8];
    #pragma unroll
    for (int o = 16; o; o >>= 1) sq += __shfl_xor_sync(0xffffffffu, sq, o);
    if ((threadIdx.x & 31) == 0) sh[threadIdx.x >> 5] = sq;
    __syncthreads();
    if (threadIdx.x == 0) {
        float t = 0; for (int i = 0; i < 8; i++) t += sh[i];
        part[b*256 + blockIdx.x] = t;
    }
}

__global__ void k_ew_mulmask_red(const float* __restrict__ x, const float* __restrict__ mk,
                                 float* __restrict__ y, float* __restrict__ part)
{
    int b = blockIdx.y;
    size_t base = (size_t)b*EPB;
    float sq = 0.f;
    #pragma unroll
    for (int r = 0; r < 8; r++) {
        int e = blockIdx.x*2048 + r*256 + threadIdx.x;
        float v = x[base + e] * mk[b*SEQ + (e >> 9)];   // D=512 -> s = e>>9
        y[base + e] = v; sq += v * v;
    }
    __shared__ float sh[8];
    #pragma unroll
    for (int o = 16; o; o >>= 1) sq += __shfl_xor_sync(0xffffffffu, sq, o);
    if ((threadIdx.x & 31) == 0) sh[threadIdx.x >> 5] = sq;
    __syncthreads();
    if (threadIdx.x == 0) {
        float t = 0; for (int i = 0; i < 8; i++) t += sh[i];
        part[b*256 + blockIdx.x] = t;
    }
}

__global__ void k_ssfinal(const float* __restrict__ part, float* __restrict__ ssf)
{
    __shared__ float sh[8];
    int b = blockIdx.x;
    float v = part[b*256 + threadIdx.x];
    #pragma unroll
    for (int o = 16; o; o >>= 1) v += __shfl_xor_sync(0xffffffffu, v, o);
    if ((threadIdx.x & 31) == 0) sh[threadIdx.x >> 5] = v;
    __syncthreads();
    if (threadIdx.x == 0) {
        float tot = sh[0]+sh[1]+sh[2]+sh[3]+sh[4]+sh[5]+sh[6]+sh[7];
        ssf[b] = NORM_SCALE_F * sqrtf(524288.f / (tot + 1e-5f));
    }
}

__global__ void k_ew_scale(float* __restrict__ y, const float* __restrict__ ssf)
{
    int b = blockIdx.y;
    float f = ssf[b];
    size_t base = (size_t)b*EPB + (size_t)blockIdx.x*2048;
    #pragma unroll
    for (int r = 0; r < 8; r++) y[base + r*256 + threadIdx.x] *= f;
}

__global__ void k_ew_mul_label(const float* __restrict__ m, const float* __restrict__ lbl,
                               float* __restrict__ v2)
{
    int b = blockIdx.y;
    size_t base = (size_t)b*EPB;
    #pragma unroll
    for (int r = 0; r < 8; r++) {
        int e = blockIdx.x*2048 + r*256 + threadIdx.x;
        v2[base + e] = m[base + e] * lbl[b*SEQ + (e >> 9)];
    }
}

// =================== host-side orchestration ===============================
namespace {

struct Ptrs {
    float *X, *mem, *V2, *T1, *T2, *W, *Wkm, *Sc, *mask, *part, *ssf;
};

inline void norm_add(float* a, float* c, float* y, const Ptrs& p)
{   // y = instnorm(a + c)
    k_ew_add_red<<<dim3(256, BATCH), 256>>>(a, c, y, p.part);
    k_ssfinal<<<BATCH, 256>>>(p.part, p.ssf);
    k_ew_scale<<<dim3(256, BATCH), 256>>>(y, p.ssf);
}

inline void proj_l2(const float* X, const float* WK, const float* bK, float* W)
{   // W = l2norm_rows(X @ WK + bK)
    k_sgemm<false><<<dim3(1, 8, BATCH), 256>>>(
        X, WK, W, SEQ, KD, DM, (size_t)SEQ*DM, 0, (size_t)SEQ*KD);
    k_bias_l2<<<dim3(SEQ, BATCH), 128>>>(W, bK);
}

inline void self_block(float* X, const float* WKs, const float* bKs, const Ptrs& p)
{
    proj_l2(X, WKs, bKs, p.W);
    k_sgemm<true><<<dim3(8, 8, BATCH), 256>>>(
        p.W, p.W, p.Sc, SEQ, SEQ, KD, (size_t)SEQ*KD, (size_t)SEQ*KD, (size_t)SEQ*SEQ);
    k_softmax<<<dim3(SEQ, BATCH), 256>>>(p.Sc);
    k_sgemm<false><<<dim3(4, 8, BATCH), 256>>>(
        p.Sc, X, p.T1, SEQ, DM, SEQ, (size_t)SEQ*SEQ, (size_t)SEQ*DM, (size_t)SEQ*DM);
    norm_add(X, p.T1, X, p);          // x = instnorm(x + attn)
}

inline void cross_block(float* X, const float* WKc, const float* bKc,
                        const float* lbl, const Ptrs& p)
{
    proj_l2(X, WKc, bKc, p.W);
    k_sgemm<true><<<dim3(8, 8, BATCH), 256>>>(
        p.W, p.Wkm, p.Sc, SEQ, SEQ, KD, (size_t)SEQ*KD, (size_t)SEQ*KD, (size_t)SEQ*SEQ);
    k_softmax<<<dim3(SEQ, BATCH), 256>>>(p.Sc);
    k_mask_gemv<<<dim3(SEQ, BATCH), 256>>>(p.Sc, lbl, p.mask);
    k_sgemm<false><<<dim3(4, 8, BATCH), 256>>>(          // t3 = aff @ (mem*pos)
        p.Sc, p.V2, p.T1, SEQ, DM, SEQ, (size_t)SEQ*SEQ, (size_t)SEQ*DM, (size_t)SEQ*DM);
    norm_add(X, p.T1, p.T1, p);                          // t4 = instnorm(x + t3)
    // t2 = instnorm(x * mask)
    k_ew_mulmask_red<<<dim3(256, BATCH), 256>>>(X, p.mask, p.T2, p.part);
    k_ssfinal<<<BATCH, 256>>>(p.part, p.ssf);
    k_ew_scale<<<dim3(256, BATCH), 256>>>(p.T2, p.ssf);
    norm_add(p.T2, p.T1, X, p);                          // x = instnorm(t2 + t4)
}

inline void run_decoder(const float* src, float* outp, const float* WKs, const float* bKs,
                        const float* WKc, const float* bKc, const float* lbl, const Ptrs& p)
{
    k_trans_in<<<dim3(32, 16, BATCH), dim3(32, 8)>>>(src, p.X);
    for (int l = 0; l < 2; l++) {
        self_block(p.X, WKs, bKs, p);
        cross_block(p.X, WKc, bKc, lbl, p);
    }
    k_trans_out<<<dim3(32, 16, BATCH), dim3(32, 8)>>>(p.X, outp);
}

} // namespace

extern "C" void kernel_launch(void* const* d_in, const int* in_sizes, int n_in,
                              void* d_out, int out_size)
{
    const float* train = (const float*)d_in[0];   // [B,D,H,W]
    const float* test  = (const float*)d_in[1];   // [B,D,H,W]
    const float* lbl   = (const float*)d_in[2];   // [B,H,W] -> [B,S]
    const float* WKs   = (const float*)d_in[3];   // [D,K]
    const float* bKs   = (const float*)d_in[4];   // [K]
    const float* WKc   = (const float*)d_in[5];
    const float* bKc   = (const float*)d_in[6];
    float* out = (float*)d_out;                   // [2,B,D,H,W]

    Ptrs p;
    cudaGetSymbolAddress((void**)&p.X,    g_X);
    cudaGetSymbolAddress((void**)&p.mem,  g_mem);
    cudaGetSymbolAddress((void**)&p.V2,   g_V2);
    cudaGetSymbolAddress((void**)&p.T1,   g_T1);
    cudaGetSymbolAddress((void**)&p.T2,   g_T2);
    cudaGetSymbolAddress((void**)&p.W,    g_W);
    cudaGetSymbolAddress((void**)&p.Wkm,  g_Wkm);
    cudaGetSymbolAddress((void**)&p.Sc,   g_Sc);
    cudaGetSymbolAddress((void**)&p.mask, g_mask);
    cudaGetSymbolAddress((void**)&p.part, g_part);
    cudaGetSymbolAddress((void**)&p.ssf,  g_ssf);

    // ---- encoder: memory = 2x self-attn layers on train_feat (in g_mem) ----
    k_trans_in<<<dim3(32, 16, BATCH), dim3(32, 8)>>>(train, p.mem);
    self_block(p.mem, WKs, bKs, p);
    self_block(p.mem, WKs, bKs, p);

    // ---- invariants shared by all decoder cross-attn calls ----
    proj_l2(p.mem, WKc, bKc, p.Wkm);                        // wk(memory)
    k_ew_mul_label<<<dim3(256, BATCH), 256>>>(p.mem, lbl, p.V2);  // memory*pos

    // ---- decoders ----
    run_decoder(train, out,                           WKs, bKs, WKc, bKc, lbl, p);
    run_decoder(test,  out + (size_t)BATCH*DM*SEQ,    WKs, bKs, WKc, bKc, lbl, p);
}

// round 4
// speedup vs baseline: 1.3449x; 1.3449x over previous
#include <cuda_runtime.h>
#include <math.h>
#include <stdint.h>

// Problem constants
#define BATCH 16
#define SEQ   1024          // H*W = 32*32
#define DM    512           // d_model
#define KD    128           // key dim
#define TEMP_F 30.0f
#define EPB   (SEQ*DM)      // elements per batch = 524288
#define NORM_SCALE_F 0.011048543456039806f   // sqrt(1/(512*16))

// ---------------- scratch (static device memory; allocation-free) ----------
__device__ __align__(16) float g_X  [BATCH*SEQ*DM];
__device__ __align__(16) float g_mem[BATCH*SEQ*DM];
__device__ __align__(16) float g_V2 [BATCH*SEQ*DM];
__device__ __align__(16) float g_T1 [BATCH*SEQ*DM];
__device__ __align__(16) float g_T2 [BATCH*SEQ*DM];
__device__ __align__(16) float g_W  [BATCH*SEQ*KD];
__device__ __align__(16) float g_Wkm[BATCH*SEQ*KD];
__device__ __align__(16) float g_Sc [BATCH*SEQ*SEQ];
__device__ float g_mask[BATCH*SEQ];
__device__ float g_part[BATCH*256];
__device__ float g_ssf [BATCH];

// ====================== tensor-core 3xTF32 GEMM ============================
// C = A @ B (TRANSB=false, B:[K,N]) or A @ B^T (TRANSB=true, B:[N,K])
// fp32 in/out, fp32-grade accuracy via hi/lo tf32 split (3 MMAs per product).
// Block tile 128x128, BK=16, 8 warps (2x4), warp tile 64x32, m16n8k8 MMA.

__device__ __forceinline__ void split_tf32(float x, uint32_t& hi, uint32_t& lo)
{
    uint32_t h;
    asm("cvt.rna.tf32.f32 %0, %1;" : "=r"(h) : "f"(x));
    float r = x - __uint_as_float(h);
    uint32_t l;
    asm("cvt.rna.tf32.f32 %0, %1;" : "=r"(l) : "f"(r));
    hi = h; lo = l;
}

__device__ __forceinline__ void mma_tf32(float* c, const uint32_t* a, const uint32_t* b)
{
    asm volatile(
        "mma.sync.aligned.m16n8k8.row.col.f32.tf32.tf32.f32 "
        "{%0,%1,%2,%3},{%4,%5,%6,%7},{%8,%9},{%0,%1,%2,%3};"
        : "+f"(c[0]), "+f"(c[1]), "+f"(c[2]), "+f"(c[3])
        : "r"(a[0]), "r"(a[1]), "r"(a[2]), "r"(a[3]), "r"(b[0]), "r"(b[1]));
}

#define CP_ASYNC16(dst_u32, src_ptr) \
    asm volatile("cp.async.cg.shared.global [%0], [%1], 16;\n" :: "r"(dst_u32), "l"(src_ptr))
#define CP_COMMIT()  asm volatile("cp.async.commit_group;\n" ::)
#define CP_WAIT_1()  asm volatile("cp.async.wait_group 1;\n" ::)
#define CP_WAIT_0()  asm volatile("cp.async.wait_group 0;\n" ::)

template<bool TRANSB>
__global__ void __launch_bounds__(256)
k_mma(const float* __restrict__ Ag, const float* __restrict__ Bg,
      float* __restrict__ Cg, int M, int N, int K,
      size_t sA, size_t sB, size_t sC)
{
    // A stage: [128 rows][16 k + pad4] ; B stage: TRANSB ? [128 n][16 k + pad4]
    //                                              : [16 k][128 n + pad4]
    __shared__ float As[2][128 * 20];
    __shared__ float Bs[2][TRANSB ? 128 * 20 : 16 * 132];

    const float* A = Ag + (size_t)blockIdx.z * sA;
    const float* B = Bg + (size_t)blockIdx.z * sB;
    float*       C = Cg + (size_t)blockIdx.z * sC;

    const int bm = blockIdx.y * 128;
    const int bn = blockIdx.x * 128;
    const int tid  = threadIdx.x;
    const int lane = tid & 31;
    const int warp = tid >> 5;
    const int wm = (warp & 1) * 64;   // warp m offset in block
    const int wn = (warp >> 1) * 32;  // warp n offset in block

    const int qid = lane >> 2;        // 0..7
    const int tig = lane & 3;         // 0..3

    auto load_stage = [&](int st, int k0) {
        // A: 128 rows x 16 floats = 512 x 16B chunks, 2 per thread
        #pragma unroll
        for (int i = 0; i < 2; i++) {
            int idx = tid + i * 256;
            int r = idx >> 2, c = (idx & 3) * 4;
            uint32_t dst = (uint32_t)__cvta_generic_to_shared(&As[st][r * 20 + c]);
            CP_ASYNC16(dst, A + (size_t)(bm + r) * K + k0 + c);
        }
        if (TRANSB) {
            #pragma unroll
            for (int i = 0; i < 2; i++) {
                int idx = tid + i * 256;
                int r = idx >> 2, c = (idx & 3) * 4;
                uint32_t dst = (uint32_t)__cvta_generic_to_shared(&Bs[st][r * 20 + c]);
                CP_ASYNC16(dst, B + (size_t)(bn + r) * K + k0 + c);
            }
        } else {
            #pragma unroll
            for (int i = 0; i < 2; i++) {
                int idx = tid + i * 256;
                int k = idx >> 5, n = (idx & 31) * 4;
                uint32_t dst = (uint32_t)__cvta_generic_to_shared(&Bs[st][k * 132 + n]);
                CP_ASYNC16(dst, B + (size_t)(k0 + k) * N + bn + n);
            }
        }
        CP_COMMIT();
    };

    float acc[4][4][4] = {};

    const int nIter = K >> 4;
    load_stage(0, 0);

    for (int it = 0; it < nIter; ++it) {
        if (it + 1 < nIter) { load_stage((it + 1) & 1, (it + 1) * 16); CP_WAIT_1(); }
        else                { CP_WAIT_0(); }
        __syncthreads();

        const int st = it & 1;
        #pragma unroll
        for (int ks = 0; ks < 2; ks++) {
            const int c0 = ks * 8 + tig;
            uint32_t ah[4][4], al[4][4];
            #pragma unroll
            for (int mi = 0; mi < 4; mi++) {
                const int r0 = wm + mi * 16 + qid;
                split_tf32(As[st][ r0      * 20 + c0    ], ah[mi][0], al[mi][0]);
                split_tf32(As[st][(r0 + 8) * 20 + c0    ], ah[mi][1], al[mi][1]);
                split_tf32(As[st][ r0      * 20 + c0 + 4], ah[mi][2], al[mi][2]);
                split_tf32(As[st][(r0 + 8) * 20 + c0 + 4], ah[mi][3], al[mi][3]);
            }
            uint32_t bh[4][2], bl[4][2];
            #pragma unroll
            for (int ni = 0; ni < 4; ni++) {
                const int n = wn + ni * 8 + qid;
                if (TRANSB) {
                    split_tf32(Bs[st][n * 20 + c0    ], bh[ni][0], bl[ni][0]);
                    split_tf32(Bs[st][n * 20 + c0 + 4], bh[ni][1], bl[ni][1]);
                } else {
                    split_tf32(Bs[st][ c0      * 132 + n], bh[ni][0], bl[ni][0]);
                    split_tf32(Bs[st][(c0 + 4) * 132 + n], bh[ni][1], bl[ni][1]);
                }
            }
            // three passes of 16 independent MMAs each (hi*hi, hi*lo, lo*hi)
            #pragma unroll
            for (int mi = 0; mi < 4; mi++)
                #pragma unroll
                for (int ni = 0; ni < 4; ni++)
                    mma_tf32(acc[mi][ni], ah[mi], bh[ni]);
            #pragma unroll
            for (int mi = 0; mi < 4; mi++)
                #pragma unroll
                for (int ni = 0; ni < 4; ni++)
                    mma_tf32(acc[mi][ni], ah[mi], bl[ni]);
            #pragma unroll
            for (int mi = 0; mi < 4; mi++)
                #pragma unroll
                for (int ni = 0; ni < 4; ni++)
                    mma_tf32(acc[mi][ni], al[mi], bh[ni]);
        }
        __syncthreads();
    }

    // epilogue: fp32 C
    #pragma unroll
    for (int mi = 0; mi < 4; mi++) {
        #pragma unroll
        for (int ni = 0; ni < 4; ni++) {
            const int r = bm + wm + mi * 16 + qid;
            const int c = bn + wn + ni * 8 + 2 * tig;
            float2 v0 = make_float2(acc[mi][ni][0], acc[mi][ni][1]);
            float2 v1 = make_float2(acc[mi][ni][2], acc[mi][ni][3]);
            *(float2*)&C[(size_t)r * N + c]       = v0;
            *(float2*)&C[(size_t)(r + 8) * N + c] = v1;
        }
    }
}

// ---------------- transposes: [B,D,S] <-> [B,S,D] ---------------------------
__global__ void k_trans_in(const float* __restrict__ in, float* __restrict__ X)
{
    __shared__ float tile[32][33];
    int b = blockIdx.z;
    int d0 = blockIdx.y * 32, s0 = blockIdx.x * 32;
    for (int r = threadIdx.y; r < 32; r += 8)
        tile[r][threadIdx.x] = in[((size_t)b*DM + d0 + r) * SEQ + s0 + threadIdx.x];
    __syncthreads();
    for (int r = threadIdx.y; r < 32; r += 8)
        X[((size_t)b*SEQ + s0 + r) * DM + d0 + threadIdx.x] = tile[threadIdx.x][r];
}

__global__ void k_trans_out(const float* __restrict__ X, float* __restrict__ out)
{
    __shared__ float tile[32][33];
    int b = blockIdx.z;
    int d0 = blockIdx.y * 32, s0 = blockIdx.x * 32;
    for (int r = threadIdx.y; r < 32; r += 8)
        tile[r][threadIdx.x] = X[((size_t)b*SEQ + s0 + r) * DM + d0 + threadIdx.x];
    __syncthreads();
    for (int r = threadIdx.y; r < 32; r += 8)
        out[((size_t)b*DM + d0 + r) * SEQ + s0 + threadIdx.x] = tile[threadIdx.x][r];
}

// ---------------- bias add + row L2 normalize on [B,S,KD] ------------------
__global__ void k_bias_l2(float* __restrict__ W, const float* __restrict__ bias)
{
    int b = blockIdx.y, s = blockIdx.x, t = threadIdx.x;   // 128 threads
    size_t idx = ((size_t)b*SEQ + s) * KD + t;
    float v = W[idx] + bias[t];
    float sq = v * v;
    #pragma unroll
    for (int o = 16; o; o >>= 1) sq += __shfl_xor_sync(0xffffffffu, sq, o);
    __shared__ float sh[4];
    if ((t & 31) == 0) sh[t >> 5] = sq;
    __syncthreads();
    float tot = sh[0] + sh[1] + sh[2] + sh[3];
    W[idx] = v / fmaxf(sqrtf(tot), 1e-12f);
}

// ---------------- row softmax with temperature on [B,S,S] ------------------
__global__ void k_softmax(float* __restrict__ Sc)
{
    __shared__ float sh1[8], sh2[8];
    int b = blockIdx.y, q = blockIdx.x, t = threadIdx.x;   // 256 threads
    float* row = Sc + ((size_t)b*SEQ + q) * SEQ;
    float v0 = row[t]        * TEMP_F;
    float v1 = row[t + 256]  * TEMP_F;
    float v2 = row[t + 512]  * TEMP_F;
    float v3 = row[t + 768]  * TEMP_F;
    float m = fmaxf(fmaxf(v0, v1), fmaxf(v2, v3));
    #pragma unroll
    for (int o = 16; o; o >>= 1) m = fmaxf(m, __shfl_xor_sync(0xffffffffu, m, o));
    if ((t & 31) == 0) sh1[t >> 5] = m;
    __syncthreads();
    m = fmaxf(fmaxf(fmaxf(sh1[0], sh1[1]), fmaxf(sh1[2], sh1[3])),
              fmaxf(fmaxf(sh1[4], sh1[5]), fmaxf(sh1[6], sh1[7])));
    v0 = __expf(v0 - m); v1 = __expf(v1 - m);
    v2 = __expf(v2 - m); v3 = __expf(v3 - m);
    float sum = v0 + v1 + v2 + v3;
    #pragma unroll
    for (int o = 16; o; o >>= 1) sum += __shfl_xor_sync(0xffffffffu, sum, o);
    if ((t & 31) == 0) sh2[t >> 5] = sum;
    __syncthreads();
    sum = sh2[0]+sh2[1]+sh2[2]+sh2[3]+sh2[4]+sh2[5]+sh2[6]+sh2[7];
    float inv = 1.f / sum;
    row[t]       = v0 * inv;
    row[t + 256] = v1 * inv;
    row[t + 512] = v2 * inv;
    row[t + 768] = v3 * inv;
}

// ---------------- mask GEMV: mask[b,q] = aff[b,q,:] . label[b,:] ------------
__global__ void k_mask_gemv(const float* __restrict__ Sc, const float* __restrict__ lbl,
                            float* __restrict__ mask)
{
    __shared__ float sh[8];
    int b = blockIdx.y, q = blockIdx.x, t = threadIdx.x;
    const float* row = Sc + ((size_t)b*SEQ + q) * SEQ;
    const float* L = lbl + (size_t)b*SEQ;
    float s = 0.f;
    #pragma unroll
    for (int i = 0; i < 4; i++) { int j = t + 256*i; s += row[j] * L[j]; }
    #pragma unroll
    for (int o = 16; o; o >>= 1) s += __shfl_xor_sync(0xffffffffu, s, o);
    if ((t & 31) == 0) sh[t >> 5] = s;
    __syncthreads();
    if (t == 0) {
        float tot = sh[0]+sh[1]+sh[2]+sh[3]+sh[4]+sh[5]+sh[6]+sh[7];
        mask[b*SEQ + q] = tot;
    }
}

// ---------------- elementwise + deterministic sumsq partials ---------------
__global__ void k_ew_add_red(const float* __restrict__ a, const float* __restrict__ c,
                             float* __restrict__ y, float* __restrict__ part)
{
    int b = blockIdx.y;
    size_t base = (size_t)b*EPB + (size_t)blockIdx.x*2048;
    float sq = 0.f;
    #pragma unroll
    for (int r = 0; r < 8; r++) {
        size_t i = base + r*256 + threadIdx.x;
        float v = a[i] + c[i];
        y[i] = v; sq += v * v;
    }
    __shared__ float sh[8];
    #pragma unroll
    for (int o = 16; o; o >>= 1) sq += __shfl_xor_sync(0xffffffffu, sq, o);
    if ((threadIdx.x & 31) == 0) sh[threadIdx.x >> 5] = sq;
    __syncthreads();
    if (threadIdx.x == 0) {
        float t = 0; for (int i = 0; i < 8; i++) t += sh[i];
        part[b*256 + blockIdx.x] = t;
    }
}

__global__ void k_ew_mulmask_red(const float* __restrict__ x, const float* __restrict__ mk,
                                 float* __restrict__ y, float* __restrict__ part)
{
    int b = blockIdx.y;
    size_t base = (size_t)b*EPB;
    float sq = 0.f;
    #pragma unroll
    for (int r = 0; r < 8; r++) {
        int e = blockIdx.x*2048 + r*256 + threadIdx.x;
        float v = x[base + e] * mk[b*SEQ + (e >> 9)];   // D=512 -> s = e>>9
        y[base + e] = v; sq += v * v;
    }
    __shared__ float sh[8];
    #pragma unroll
    for (int o = 16; o; o >>= 1) sq += __shfl_xor_sync(0xffffffffu, sq, o);
    if ((threadIdx.x & 31) == 0) sh[threadIdx.x >> 5] = sq;
    __syncthreads();
    if (threadIdx.x == 0) {
        float t = 0; for (int i = 0; i < 8; i++) t += sh[i];
        part[b*256 + blockIdx.x] = t;
    }
}

__global__ void k_ssfinal(const float* __restrict__ part, float* __restrict__ ssf)
{
    __shared__ float sh[8];
    int b = blockIdx.x;
    float v = part[b*256 + threadIdx.x];
    #pragma unroll
    for (int o = 16; o; o >>= 1) v += __shfl_xor_sync(0xffffffffu, v, o);
    if ((threadIdx.x & 31) == 0) sh[threadIdx.x >> 5] = v;
    __syncthreads();
    if (threadIdx.x == 0) {
        float tot = sh[0]+sh[1]+sh[2]+sh[3]+sh[4]+sh[5]+sh[6]+sh[7];
        ssf[b] = NORM_SCALE_F * sqrtf(524288.f / (tot + 1e-5f));
    }
}

__global__ void k_ew_scale(float* __restrict__ y, const float* __restrict__ ssf)
{
    int b = blockIdx.y;
    float f = ssf[b];
    size_t base = (size_t)b*EPB + (size_t)blockIdx.x*2048;
    #pragma unroll
    for (int r = 0; r < 8; r++) y[base + r*256 + threadIdx.x] *= f;
}

__global__ void k_ew_mul_label(const float* __restrict__ m, const float* __restrict__ lbl,
                               float* __restrict__ v2)
{
    int b = blockIdx.y;
    size_t base = (size_t)b*EPB;
    #pragma unroll
    for (int r = 0; r < 8; r++) {
        int e = blockIdx.x*2048 + r*256 + threadIdx.x;
        v2[base + e] = m[base + e] * lbl[b*SEQ + (e >> 9)];
    }
}

// =================== host-side orchestration ===============================
namespace {

struct Ptrs {
    float *X, *mem, *V2, *T1, *T2, *W, *Wkm, *Sc, *mask, *part, *ssf;
};

inline void norm_add(float* a, float* c, float* y, const Ptrs& p)
{   // y = instnorm(a + c)
    k_ew_add_red<<<dim3(256, BATCH), 256>>>(a, c, y, p.part);
    k_ssfinal<<<BATCH, 256>>>(p.part, p.ssf);
    k_ew_scale<<<dim3(256, BATCH), 256>>>(y, p.ssf);
}

inline void proj_l2(const float* X, const float* WK, const float* bK, float* W)
{   // W = l2norm_rows(X @ WK + bK)
    k_mma<false><<<dim3(1, 8, BATCH), 256>>>(
        X, WK, W, SEQ, KD, DM, (size_t)SEQ*DM, 0, (size_t)SEQ*KD);
    k_bias_l2<<<dim3(SEQ, BATCH), 128>>>(W, bK);
}

inline void self_block(float* X, const float* WKs, const float* bKs, const Ptrs& p)
{
    proj_l2(X, WKs, bKs, p.W);
    k_mma<true><<<dim3(8, 8, BATCH), 256>>>(
        p.W, p.W, p.Sc, SEQ, SEQ, KD, (size_t)SEQ*KD, (size_t)SEQ*KD, (size_t)SEQ*SEQ);
    k_softmax<<<dim3(SEQ, BATCH), 256>>>(p.Sc);
    k_mma<false><<<dim3(4, 8, BATCH), 256>>>(
        p.Sc, X, p.T1, SEQ, DM, SEQ, (size_t)SEQ*SEQ, (size_t)SEQ*DM, (size_t)SEQ*DM);
    norm_add(X, p.T1, X, p);          // x = instnorm(x + attn)
}

inline void cross_block(float* X, const float* WKc, const float* bKc,
                        const float* lbl, const Ptrs& p)
{
    proj_l2(X, WKc, bKc, p.W);
    k_mma<true><<<dim3(8, 8, BATCH), 256>>>(
        p.W, p.Wkm, p.Sc, SEQ, SEQ, KD, (size_t)SEQ*KD, (size_t)SEQ*KD, (size_t)SEQ*SEQ);
    k_softmax<<<dim3(SEQ, BATCH), 256>>>(p.Sc);
    k_mask_gemv<<<dim3(SEQ, BATCH), 256>>>(p.Sc, lbl, p.mask);
    k_mma<false><<<dim3(4, 8, BATCH), 256>>>(            // t3 = aff @ (mem*pos)
        p.Sc, p.V2, p.T1, SEQ, DM, SEQ, (size_t)SEQ*SEQ, (size_t)SEQ*DM, (size_t)SEQ*DM);
    norm_add(X, p.T1, p.T1, p);                          // t4 = instnorm(x + t3)
    // t2 = instnorm(x * mask)
    k_ew_mulmask_red<<<dim3(256, BATCH), 256>>>(X, p.mask, p.T2, p.part);
    k_ssfinal<<<BATCH, 256>>>(p.part, p.ssf);
    k_ew_scale<<<dim3(256, BATCH), 256>>>(p.T2, p.ssf);
    norm_add(p.T2, p.T1, X, p);                          // x = instnorm(t2 + t4)
}

inline void run_decoder(const float* src, float* outp, const float* WKs, const float* bKs,
                        const float* WKc, const float* bKc, const float* lbl, const Ptrs& p)
{
    k_trans_in<<<dim3(32, 16, BATCH), dim3(32, 8)>>>(src, p.X);
    for (int l = 0; l < 2; l++) {
        self_block(p.X, WKs, bKs, p);
        cross_block(p.X, WKc, bKc, lbl, p);
    }
    k_trans_out<<<dim3(32, 16, BATCH), dim3(32, 8)>>>(p.X, outp);
}

} // namespace

extern "C" void kernel_launch(void* const* d_in, const int* in_sizes, int n_in,
                              void* d_out, int out_size)
{
    const float* train = (const float*)d_in[0];   // [B,D,H,W]
    const float* test  = (const float*)d_in[1];   // [B,D,H,W]
    const float* lbl   = (const float*)d_in[2];   // [B,H,W] -> [B,S]
    const float* WKs   = (const float*)d_in[3];   // [D,K]
    const float* bKs   = (const float*)d_in[4];   // [K]
    const float* WKc   = (const float*)d_in[5];
    const float* bKc   = (const float*)d_in[6];
    float* out = (float*)d_out;                   // [2,B,D,H,W]

    Ptrs p;
    cudaGetSymbolAddress((void**)&p.X,    g_X);
    cudaGetSymbolAddress((void**)&p.mem,  g_mem);
    cudaGetSymbolAddress((void**)&p.V2,   g_V2);
    cudaGetSymbolAddress((void**)&p.T1,   g_T1);
    cudaGetSymbolAddress((void**)&p.T2,   g_T2);
    cudaGetSymbolAddress((void**)&p.W,    g_W);
    cudaGetSymbolAddress((void**)&p.Wkm,  g_Wkm);
    cudaGetSymbolAddress((void**)&p.Sc,   g_Sc);
    cudaGetSymbolAddress((void**)&p.mask, g_mask);
    cudaGetSymbolAddress((void**)&p.part, g_part);
    cudaGetSymbolAddress((void**)&p.ssf,  g_ssf);

    // ---- encoder: memory = 2x self-attn layers on train_feat (in g_mem) ----
    k_trans_in<<<dim3(32, 16, BATCH), dim3(32, 8)>>>(train, p.mem);
    self_block(p.mem, WKs, bKs, p);
    self_block(p.mem, WKs, bKs, p);

    // ---- invariants shared by all decoder cross-attn calls ----
    proj_l2(p.mem, WKc, bKc, p.Wkm);                        // wk(memory)
    k_ew_mul_label<<<dim3(256, BATCH), 256>>>(p.mem, lbl, p.V2);  // memory*pos

    // ---- decoders ----
    run_decoder(train, out,                           WKs, bKs, WKc, bKc, lbl, p);
    run_decoder(test,  out + (size_t)BATCH*DM*SEQ,    WKs, bKs, WKc, bKc, lbl, p);
}

// round 5
// speedup vs baseline: 2.2376x; 1.6638x over previous
#include <cuda_runtime.h>
#include <cuda_bf16.h>
#include <math.h>
#include <stdint.h>

#define BATCH 16
#define SEQ   1024
#define DM    512
#define KD    128
#define TEMP_F 30.0f
#define EPB   (SEQ*DM)
#define NORM_SCALE_F 0.011048543456039806f   // sqrt(1/(512*16))

typedef __nv_bfloat16 bf16;

// ---------------- scratch (static device memory; allocation-free) ----------
__device__ __align__(16) float g_X   [BATCH*SEQ*DM];
__device__ __align__(16) float g_mem [BATCH*SEQ*DM];
__device__ __align__(16) float g_V2  [BATCH*SEQ*DM];
__device__ __align__(16) float g_T1  [BATCH*SEQ*DM];
__device__ __align__(16) float g_T2  [BATCH*SEQ*DM];
__device__ __align__(16) float g_Wtmp[BATCH*SEQ*KD];
__device__ __align__(16) float g_Sc  [BATCH*SEQ*SEQ];
__device__ float g_mask[BATCH*SEQ];
__device__ float g_part[BATCH*256];
__device__ float g_ssf [BATCH];
// bf16 hi/lo split operand buffers
__device__ __align__(16) bf16 g_Xh  [BATCH*SEQ*DM], g_Xl  [BATCH*SEQ*DM];
__device__ __align__(16) bf16 g_Xth [BATCH*SEQ*DM], g_Xtl [BATCH*SEQ*DM];   // X^T  [B][D][S]
__device__ __align__(16) bf16 g_V2th[BATCH*SEQ*DM], g_V2tl[BATCH*SEQ*DM];   // V2^T [B][D][S]
__device__ __align__(16) bf16 g_Wh  [BATCH*SEQ*KD], g_Wl  [BATCH*SEQ*KD];
__device__ __align__(16) bf16 g_Wkmh[BATCH*SEQ*KD], g_Wkml[BATCH*SEQ*KD];
__device__ __align__(16) bf16 g_Sch [BATCH*SEQ*SEQ], g_Scl[BATCH*SEQ*SEQ];
__device__ __align__(16) bf16 g_WKth[2*KD*DM], g_WKtl[2*KD*DM];             // WK^T [K][D]

__device__ __forceinline__ void bsplit(float x, bf16& h, bf16& l)
{
    bf16 hh = __float2bfloat16(x);
    h = hh;
    l = __float2bfloat16(x - __bfloat162float(hh));
}

// ====================== pure-bf16 3-pass tensor-core GEMM ==================
// C = (Ah+Al) @ (Bh+Bl)^T  (drop Al*Bl).  A:[M,K] row-major, B:[N,K] row-major.
// Block 128x128, BK=32, 8 warps (2x4), warp tile 64x32, mma m16n8k16 bf16.

__device__ __forceinline__ void mma_bf16(float* c, const uint32_t* a, const uint32_t* b)
{
    asm volatile(
        "mma.sync.aligned.m16n8k16.row.col.f32.bf16.bf16.f32 "
        "{%0,%1,%2,%3},{%4,%5,%6,%7},{%8,%9},{%0,%1,%2,%3};"
        : "+f"(c[0]), "+f"(c[1]), "+f"(c[2]), "+f"(c[3])
        : "r"(a[0]), "r"(a[1]), "r"(a[2]), "r"(a[3]), "r"(b[0]), "r"(b[1]));
}

#define CP_ASYNC16(dst_u32, src_ptr) \
    asm volatile("cp.async.cg.shared.global [%0], [%1], 16;\n" :: "r"(dst_u32), "l"(src_ptr))
#define CP_COMMIT()  asm volatile("cp.async.commit_group;\n" ::)
#define CP_WAIT_1()  asm volatile("cp.async.wait_group 1;\n" ::)
#define CP_WAIT_0()  asm volatile("cp.async.wait_group 0;\n" ::)

// smem: per stage 4 tiles (Ah,Al,Bh,Bl), each [128 rows][20 words] (32 bf16 + pad)
#define TILE_W   2560                 // words per tile
#define STAGE_W  (4*TILE_W)           // 10240 words
#define GEMM_SMEM_BYTES (2*STAGE_W*4) // 81920 B

__global__ void __launch_bounds__(256, 2)
k_gemm(const bf16* __restrict__ Ahg, const bf16* __restrict__ Alg,
       const bf16* __restrict__ Bhg, const bf16* __restrict__ Blg,
       float* __restrict__ Cg, int M, int N, int K,
       size_t sA, size_t sB, size_t sC)
{
    extern __shared__ uint32_t sm[];
    const bf16* Ah = Ahg + (size_t)blockIdx.z * sA;
    const bf16* Al = Alg + (size_t)blockIdx.z * sA;
    const bf16* Bh = Bhg + (size_t)blockIdx.z * sB;
    const bf16* Bl = Blg + (size_t)blockIdx.z * sB;
    float*      C  = Cg  + (size_t)blockIdx.z * sC;

    const int bm = blockIdx.y * 128;
    const int bn = blockIdx.x * 128;
    const int tid  = threadIdx.x;
    const int lane = tid & 31;
    const int warp = tid >> 5;
    const int wm = (warp & 1) * 64;
    const int wn = (warp >> 1) * 32;
    const int qid = lane >> 2;
    const int tig = lane & 3;

    const uint32_t sbase = (uint32_t)__cvta_generic_to_shared(sm);

    auto load_stage = [&](int st, int k0) {
        uint32_t stb = sbase + st * (STAGE_W * 4);
        #pragma unroll
        for (int h = 0; h < 2; h++) {
            int idx = tid + h * 256;          // 0..511
            int rr = idx >> 2, cc = idx & 3;  // row 0..127, 16B-chunk 0..3
            uint32_t woff = (rr * 20 + cc * 4) * 4;
            size_t ga = (size_t)(bm + rr) * K + k0 + cc * 8;
            size_t gb = (size_t)(bn + rr) * K + k0 + cc * 8;
            CP_ASYNC16(stb + 0*TILE_W*4 + woff, Ah + ga);
            CP_ASYNC16(stb + 1*TILE_W*4 + woff, Al + ga);
            CP_ASYNC16(stb + 2*TILE_W*4 + woff, Bh + gb);
            CP_ASYNC16(stb + 3*TILE_W*4 + woff, Bl + gb);
        }
        CP_COMMIT();
    };

    float acc[4][4][4] = {};
    const int nIter = K >> 5;
    load_stage(0, 0);

    for (int it = 0; it < nIter; ++it) {
        if (it + 1 < nIter) { load_stage((it + 1) & 1, (it + 1) * 32); CP_WAIT_1(); }
        else                { CP_WAIT_0(); }
        __syncthreads();

        const uint32_t* As_h = sm + (it & 1) * STAGE_W;
        const uint32_t* As_l = As_h + TILE_W;
        const uint32_t* Bs_h = As_h + 2*TILE_W;
        const uint32_t* Bs_l = As_h + 3*TILE_W;

        #pragma unroll
        for (int ks = 0; ks < 2; ks++) {
            const int kw = ks * 8 + tig;
            uint32_t ah[4][4], bh[4][2], bl[4][2];
            #pragma unroll
            for (int mi = 0; mi < 4; mi++) {
                int b0 = (wm + mi*16 + qid) * 20 + kw;
                ah[mi][0] = As_h[b0];       ah[mi][1] = As_h[b0 + 160];
                ah[mi][2] = As_h[b0 + 4];   ah[mi][3] = As_h[b0 + 164];
            }
            #pragma unroll
            for (int ni = 0; ni < 4; ni++) {
                int b0 = (wn + ni*8 + qid) * 20 + kw;
                bh[ni][0] = Bs_h[b0];  bh[ni][1] = Bs_h[b0 + 4];
                bl[ni][0] = Bs_l[b0];  bl[ni][1] = Bs_l[b0 + 4];
            }
            #pragma unroll
            for (int mi = 0; mi < 4; mi++)
                #pragma unroll
                for (int ni = 0; ni < 4; ni++)
                    mma_bf16(acc[mi][ni], ah[mi], bh[ni]);
            #pragma unroll
            for (int mi = 0; mi < 4; mi++)
                #pragma unroll
                for (int ni = 0; ni < 4; ni++)
                    mma_bf16(acc[mi][ni], ah[mi], bl[ni]);
            uint32_t al[4][4];
            #pragma unroll
            for (int mi = 0; mi < 4; mi++) {
                int b0 = (wm + mi*16 + qid) * 20 + kw;
                al[mi][0] = As_l[b0];       al[mi][1] = As_l[b0 + 160];
                al[mi][2] = As_l[b0 + 4];   al[mi][3] = As_l[b0 + 164];
            }
            #pragma unroll
            for (int mi = 0; mi < 4; mi++)
                #pragma unroll
                for (int ni = 0; ni < 4; ni++)
                    mma_bf16(acc[mi][ni], al[mi], bh[ni]);
        }
        __syncthreads();
    }

    #pragma unroll
    for (int mi = 0; mi < 4; mi++) {
        #pragma unroll
        for (int ni = 0; ni < 4; ni++) {
            const int r = bm + wm + mi * 16 + qid;
            const int c = bn + wn + ni * 8 + 2 * tig;
            *(float2*)&C[(size_t)r * N + c]       = make_float2(acc[mi][ni][0], acc[mi][ni][1]);
            *(float2*)&C[(size_t)(r + 8) * N + c] = make_float2(acc[mi][ni][2], acc[mi][ni][3]);
        }
    }
}

// ---------------- weight transpose + split: WK[D][K] -> WKt[K][D] ----------
__global__ void k_split_wt(const float* __restrict__ Wk, bf16* __restrict__ th,
                           bf16* __restrict__ tl)
{
    __shared__ float tile[32][33];
    int k0 = blockIdx.x * 32, d0 = blockIdx.y * 32;
    for (int r = threadIdx.y; r < 32; r += 8)
        tile[r][threadIdx.x] = Wk[(size_t)(d0 + r) * KD + k0 + threadIdx.x];
    __syncthreads();
    for (int r = threadIdx.y; r < 32; r += 8) {
        size_t idx = (size_t)(k0 + r) * DM + d0 + threadIdx.x;
        bsplit(tile[threadIdx.x][r], th[idx], tl[idx]);
    }
}

// ---------------- transposes ------------------------------------------------
__global__ void k_trans_in(const float* __restrict__ in, float* __restrict__ X,
                           bf16* __restrict__ Xh, bf16* __restrict__ Xl)
{
    __shared__ float tile[32][33];
    int b = blockIdx.z;
    int d0 = blockIdx.y * 32, s0 = blockIdx.x * 32;
    for (int r = threadIdx.y; r < 32; r += 8)
        tile[r][threadIdx.x] = in[((size_t)b*DM + d0 + r) * SEQ + s0 + threadIdx.x];
    __syncthreads();
    for (int r = threadIdx.y; r < 32; r += 8) {
        float v = tile[threadIdx.x][r];
        size_t idx = ((size_t)b*SEQ + s0 + r) * DM + d0 + threadIdx.x;
        X[idx] = v;
        bsplit(v, Xh[idx], Xl[idx]);
    }
}

__global__ void k_trans_out(const float* __restrict__ X, float* __restrict__ out)
{
    __shared__ float tile[32][33];
    int b = blockIdx.z;
    int d0 = blockIdx.y * 32, s0 = blockIdx.x * 32;
    for (int r = threadIdx.y; r < 32; r += 8)
        tile[r][threadIdx.x] = X[((size_t)b*SEQ + s0 + r) * DM + d0 + threadIdx.x];
    __syncthreads();
    for (int r = threadIdx.y; r < 32; r += 8)
        out[((size_t)b*DM + d0 + r) * SEQ + s0 + threadIdx.x] = tile[threadIdx.x][r];
}

// X[b][S][D] -> Xt hi/lo [b][D][S] (bf16 split)
__global__ void k_tsplit(const float* __restrict__ X, bf16* __restrict__ th,
                         bf16* __restrict__ tl)
{
    __shared__ float tile[32][33];
    int b = blockIdx.z;
    int s0 = blockIdx.x * 32, d0 = blockIdx.y * 32;
    for (int r = threadIdx.y; r < 32; r += 8)
        tile[r][threadIdx.x] = X[((size_t)b*SEQ + s0 + r) * DM + d0 + threadIdx.x];
    __syncthreads();
    for (int r = threadIdx.y; r < 32; r += 8) {
        size_t idx = ((size_t)b*DM + d0 + r) * SEQ + s0 + threadIdx.x;
        bsplit(tile[threadIdx.x][r], th[idx], tl[idx]);
    }
}

// ---------------- bias add + row L2 normalize -> bf16 hi/lo ----------------
__global__ void k_bias_l2(const float* __restrict__ Wt, const float* __restrict__ bias,
                          bf16* __restrict__ Wh, bf16* __restrict__ Wl)
{
    int b = blockIdx.y, s = blockIdx.x, t = threadIdx.x;   // 128 threads
    size_t idx = ((size_t)b*SEQ + s) * KD + t;
    float v = Wt[idx] + bias[t];
    float sq = v * v;
    #pragma unroll
    for (int o = 16; o; o >>= 1) sq += __shfl_xor_sync(0xffffffffu, sq, o);
    __shared__ float sh[4];
    if ((t & 31) == 0) sh[t >> 5] = sq;
    __syncthreads();
    float tot = sh[0] + sh[1] + sh[2] + sh[3];
    float o = v / fmaxf(sqrtf(tot), 1e-12f);
    bsplit(o, Wh[idx], Wl[idx]);
}

// ---------------- softmax: fp32 scores in -> bf16 hi/lo probs out ----------
__global__ void k_softmax(const float* __restrict__ Sc, bf16* __restrict__ Ph,
                          bf16* __restrict__ Pl)
{
    __shared__ float sh1[8], sh2[8];
    int b = blockIdx.y, q = blockIdx.x, t = threadIdx.x;   // 256 threads
    size_t ro = ((size_t)b*SEQ + q) * SEQ;
    const float* row = Sc + ro;
    float v0 = row[t]       * TEMP_F;
    float v1 = row[t + 256] * TEMP_F;
    float v2 = row[t + 512] * TEMP_F;
    float v3 = row[t + 768] * TEMP_F;
    float m = fmaxf(fmaxf(v0, v1), fmaxf(v2, v3));
    #pragma unroll
    for (int o = 16; o; o >>= 1) m = fmaxf(m, __shfl_xor_sync(0xffffffffu, m, o));
    if ((t & 31) == 0) sh1[t >> 5] = m;
    __syncthreads();
    m = fmaxf(fmaxf(fmaxf(sh1[0], sh1[1]), fmaxf(sh1[2], sh1[3])),
              fmaxf(fmaxf(sh1[4], sh1[5]), fmaxf(sh1[6], sh1[7])));
    v0 = __expf(v0 - m); v1 = __expf(v1 - m);
    v2 = __expf(v2 - m); v3 = __expf(v3 - m);
    float sum = v0 + v1 + v2 + v3;
    #pragma unroll
    for (int o = 16; o; o >>= 1) sum += __shfl_xor_sync(0xffffffffu, sum, o);
    if ((t & 31) == 0) sh2[t >> 5] = sum;
    __syncthreads();
    sum = sh2[0]+sh2[1]+sh2[2]+sh2[3]+sh2[4]+sh2[5]+sh2[6]+sh2[7];
    float inv = 1.f / sum;
    bsplit(v0 * inv, Ph[ro + t],       Pl[ro + t]);
    bsplit(v1 * inv, Ph[ro + t + 256], Pl[ro + t + 256]);
    bsplit(v2 * inv, Ph[ro + t + 512], Pl[ro + t + 512]);
    bsplit(v3 * inv, Ph[ro + t + 768], Pl[ro + t + 768]);
}

// ---------------- mask GEMV from bf16 probs --------------------------------
__global__ void k_mask_gemv(const bf16* __restrict__ Ph, const bf16* __restrict__ Pl,
                            const float* __restrict__ lbl, float* __restrict__ mask)
{
    __shared__ float sh[8];
    int b = blockIdx.y, q = blockIdx.x, t = threadIdx.x;
    size_t ro = ((size_t)b*SEQ + q) * SEQ;
    const float* L = lbl + (size_t)b*SEQ;
    float s = 0.f;
    #pragma unroll
    for (int i = 0; i < 4; i++) {
        int j = t + 256*i;
        s += (__bfloat162float(Ph[ro + j]) + __bfloat162float(Pl[ro + j])) * L[j];
    }
    #pragma unroll
    for (int o = 16; o; o >>= 1) s += __shfl_xor_sync(0xffffffffu, s, o);
    if ((t & 31) == 0) sh[t >> 5] = s;
    __syncthreads();
    if (t == 0) {
        mask[b*SEQ + q] = sh[0]+sh[1]+sh[2]+sh[3]+sh[4]+sh[5]+sh[6]+sh[7];
    }
}

// ---------------- elementwise + deterministic sumsq partials ---------------
__global__ void k_ew_add_red(const float* __restrict__ a, const float* __restrict__ c,
                             float* __restrict__ y, float* __restrict__ part)
{
    int b = blockIdx.y;
    size_t base = (size_t)b*EPB + (size_t)blockIdx.x*2048;
    float sq = 0.f;
    #pragma unroll
    for (int r = 0; r < 8; r++) {
        size_t i = base + r*256 + threadIdx.x;
        float v = a[i] + c[i];
        y[i] = v; sq += v * v;
    }
    __shared__ float sh[8];
    #pragma unroll
    for (int o = 16; o; o >>= 1) sq += __shfl_xor_sync(0xffffffffu, sq, o);
    if ((threadIdx.x & 31) == 0) sh[threadIdx.x >> 5] = sq;
    __syncthreads();
    if (threadIdx.x == 0) {
        float t = 0; for (int i = 0; i < 8; i++) t += sh[i];
        part[b*256 + blockIdx.x] = t;
    }
}

__global__ void k_ew_mulmask_red(const float* __restrict__ x, const float* __restrict__ mk,
                                 float* __restrict__ y, float* __restrict__ part)
{
    int b = blockIdx.y;
    size_t base = (size_t)b*EPB;
    float sq = 0.f;
    #pragma unroll
    for (int r = 0; r < 8; r++) {
        int e = blockIdx.x*2048 + r*256 + threadIdx.x;
        float v = x[base + e] * mk[b*SEQ + (e >> 9)];
        y[base + e] = v; sq += v * v;
    }
    __shared__ float sh[8];
    #pragma unroll
    for (int o = 16; o; o >>= 1) sq += __shfl_xor_sync(0xffffffffu, sq, o);
    if ((threadIdx.x & 31) == 0) sh[threadIdx.x >> 5] = sq;
    __syncthreads();
    if (threadIdx.x == 0) {
        float t = 0; for (int i = 0; i < 8; i++) t += sh[i];
        part[b*256 + blockIdx.x] = t;
    }
}

__global__ void k_ssfinal(const float* __restrict__ part, float* __restrict__ ssf)
{
    __shared__ float sh[8];
    int b = blockIdx.x;
    float v = part[b*256 + threadIdx.x];
    #pragma unroll
    for (int o = 16; o; o >>= 1) v += __shfl_xor_sync(0xffffffffu, v, o);
    if ((threadIdx.x & 31) == 0) sh[threadIdx.x >> 5] = v;
    __syncthreads();
    if (threadIdx.x == 0) {
        float tot = sh[0]+sh[1]+sh[2]+sh[3]+sh[4]+sh[5]+sh[6]+sh[7];
        ssf[b] = NORM_SCALE_F * sqrtf(524288.f / (tot + 1e-5f));
    }
}

__global__ void k_ew_scale(float* __restrict__ y, const float* __restrict__ ssf)
{
    int b = blockIdx.y;
    float f = ssf[b];
    size_t base = (size_t)b*EPB + (size_t)blockIdx.x*2048;
    #pragma unroll
    for (int r = 0; r < 8; r++) y[base + r*256 + threadIdx.x] *= f;
}

__global__ void k_ew_scale_emit(float* __restrict__ y, const float* __restrict__ ssf,
                                bf16* __restrict__ yh, bf16* __restrict__ yl)
{
    int b = blockIdx.y;
    float f = ssf[b];
    size_t base = (size_t)b*EPB + (size_t)blockIdx.x*2048;
    #pragma unroll
    for (int r = 0; r < 8; r++) {
        size_t i = base + r*256 + threadIdx.x;
        float v = y[i] * f;
        y[i] = v;
        bsplit(v, yh[i], yl[i]);
    }
}

__global__ void k_ew_mul_label(const float* __restrict__ m, const float* __restrict__ lbl,
                               float* __restrict__ v2)
{
    int b = blockIdx.y;
    size_t base = (size_t)b*EPB;
    #pragma unroll
    for (int r = 0; r < 8; r++) {
        int e = blockIdx.x*2048 + r*256 + threadIdx.x;
        v2[base + e] = m[base + e] * lbl[b*SEQ + (e >> 9)];
    }
}

// =================== host-side orchestration ===============================
namespace {

struct Ptrs {
    float *X, *mem, *V2, *T1, *T2, *Wtmp, *Sc, *mask, *part, *ssf;
    bf16 *Xh, *Xl, *Xth, *Xtl, *V2th, *V2tl, *Wh, *Wl, *Wkmh, *Wkml,
         *Sch, *Scl, *WKth, *WKtl;
};

inline void norm_add(float* a, float* c, float* y, bool emit, const Ptrs& p)
{   // y = instnorm(a + c), optionally emitting bf16 split of y
    k_ew_add_red<<<dim3(256, BATCH), 256>>>(a, c, y, p.part);
    k_ssfinal<<<BATCH, 256>>>(p.part, p.ssf);
    if (emit) k_ew_scale_emit<<<dim3(256, BATCH), 256>>>(y, p.ssf, p.Xh, p.Xl);
    else      k_ew_scale<<<dim3(256, BATCH), 256>>>(y, p.ssf);
}

inline void proj_l2(int wsel, const float* bK, bf16* outH, bf16* outL, const Ptrs& p)
{   // out = l2norm_rows(X @ WK + bK), X given by p.Xh/p.Xl
    k_gemm<<<dim3(1, 8, BATCH), 256, GEMM_SMEM_BYTES>>>(
        p.Xh, p.Xl, p.WKth + (size_t)wsel*KD*DM, p.WKtl + (size_t)wsel*KD*DM,
        p.Wtmp, SEQ, KD, DM, (size_t)SEQ*DM, 0, (size_t)SEQ*KD);
    k_bias_l2<<<dim3(SEQ, BATCH), 128>>>(p.Wtmp, bK, outH, outL);
}

inline void self_block(float* X, const float* bKs, const Ptrs& p)
{
    // V = x (pre-norm x) transposed + split
    k_tsplit<<<dim3(32, 16, BATCH), dim3(32, 8)>>>(X, p.Xth, p.Xtl);
    proj_l2(0, bKs, p.Wh, p.Wl, p);
    k_gemm<<<dim3(8, 8, BATCH), 256, GEMM_SMEM_BYTES>>>(     // scores
        p.Wh, p.Wl, p.Wh, p.Wl, p.Sc, SEQ, SEQ, KD,
        (size_t)SEQ*KD, (size_t)SEQ*KD, (size_t)SEQ*SEQ);
    k_softmax<<<dim3(SEQ, BATCH), 256>>>(p.Sc, p.Sch, p.Scl);
    k_gemm<<<dim3(4, 8, BATCH), 256, GEMM_SMEM_BYTES>>>(     // attn @ V
        p.Sch, p.Scl, p.Xth, p.Xtl, p.T1, SEQ, DM, SEQ,
        (size_t)SEQ*SEQ, (size_t)DM*SEQ, (size_t)SEQ*DM);
    norm_add(X, p.T1, X, true, p);     // x = instnorm(x + attn), emit split
}

inline void cross_block(float* X, const float* bKc, const float* lbl, const Ptrs& p)
{
    proj_l2(1, bKc, p.Wh, p.Wl, p);
    k_gemm<<<dim3(8, 8, BATCH), 256, GEMM_SMEM_BYTES>>>(     // scores vs memory
        p.Wh, p.Wl, p.Wkmh, p.Wkml, p.Sc, SEQ, SEQ, KD,
        (size_t)SEQ*KD, (size_t)SEQ*KD, (size_t)SEQ*SEQ);
    k_softmax<<<dim3(SEQ, BATCH), 256>>>(p.Sc, p.Sch, p.Scl);
    k_mask_gemv<<<dim3(SEQ, BATCH), 256>>>(p.Sch, p.Scl, lbl, p.mask);
    k_gemm<<<dim3(4, 8, BATCH), 256, GEMM_SMEM_BYTES>>>(     // t3 = aff @ (mem*pos)
        p.Sch, p.Scl, p.V2th, p.V2tl, p.T1, SEQ, DM, SEQ,
        (size_t)SEQ*SEQ, (size_t)DM*SEQ, (size_t)SEQ*DM);
    norm_add(X, p.T1, p.T1, false, p);                       // t4 = instnorm(x + t3)
    k_ew_mulmask_red<<<dim3(256, BATCH), 256>>>(X, p.mask, p.T2, p.part);
    k_ssfinal<<<BATCH, 256>>>(p.part, p.ssf);
    k_ew_scale<<<dim3(256, BATCH), 256>>>(p.T2, p.ssf);      // t2 = instnorm(x*mask)
    norm_add(p.T2, p.T1, X, true, p);                        // x = instnorm(t2+t4), emit
}

inline void run_decoder(const float* src, float* outp, const float* bKs,
                        const float* bKc, const float* lbl, const Ptrs& p)
{
    k_trans_in<<<dim3(32, 16, BATCH), dim3(32, 8)>>>(src, p.X, p.Xh, p.Xl);
    for (int l = 0; l < 2; l++) {
        self_block(p.X, bKs, p);
        cross_block(p.X, bKc, lbl, p);
    }
    k_trans_out<<<dim3(32, 16, BATCH), dim3(32, 8)>>>(p.X, outp);
}

} // namespace

extern "C" void kernel_launch(void* const* d_in, const int* in_sizes, int n_in,
                              void* d_out, int out_size)
{
    const float* train = (const float*)d_in[0];
    const float* test  = (const float*)d_in[1];
    const float* lbl   = (const float*)d_in[2];
    const float* WKs   = (const float*)d_in[3];
    const float* bKs   = (const float*)d_in[4];
    const float* WKc   = (const float*)d_in[5];
    const float* bKc   = (const float*)d_in[6];
    float* out = (float*)d_out;

    cudaFuncSetAttribute(k_gemm, cudaFuncAttributeMaxDynamicSharedMemorySize,
                         GEMM_SMEM_BYTES);

    Ptrs p;
    cudaGetSymbolAddress((void**)&p.X,    g_X);
    cudaGetSymbolAddress((void**)&p.mem,  g_mem);
    cudaGetSymbolAddress((void**)&p.V2,   g_V2);
    cudaGetSymbolAddress((void**)&p.T1,   g_T1);
    cudaGetSymbolAddress((void**)&p.T2,   g_T2);
    cudaGetSymbolAddress((void**)&p.Wtmp, g_Wtmp);
    cudaGetSymbolAddress((void**)&p.Sc,   g_Sc);
    cudaGetSymbolAddress((void**)&p.mask, g_mask);
    cudaGetSymbolAddress((void**)&p.part, g_part);
    cudaGetSymbolAddress((void**)&p.ssf,  g_ssf);
    cudaGetSymbolAddress((void**)&p.Xh,   g_Xh);
    cudaGetSymbolAddress((void**)&p.Xl,   g_Xl);
    cudaGetSymbolAddress((void**)&p.Xth,  g_Xth);
    cudaGetSymbolAddress((void**)&p.Xtl,  g_Xtl);
    cudaGetSymbolAddress((void**)&p.V2th, g_V2th);
    cudaGetSymbolAddress((void**)&p.V2tl, g_V2tl);
    cudaGetSymbolAddress((void**)&p.Wh,   g_Wh);
    cudaGetSymbolAddress((void**)&p.Wl,   g_Wl);
    cudaGetSymbolAddress((void**)&p.Wkmh, g_Wkmh);
    cudaGetSymbolAddress((void**)&p.Wkml, g_Wkml);
    cudaGetSymbolAddress((void**)&p.Sch,  g_Sch);
    cudaGetSymbolAddress((void**)&p.Scl,  g_Scl);
    cudaGetSymbolAddress((void**)&p.WKth, g_WKth);
    cudaGetSymbolAddress((void**)&p.WKtl, g_WKtl);

    // ---- weight transpose+split (cheap, every call; deterministic) ----
    k_split_wt<<<dim3(4, 16), dim3(32, 8)>>>(WKs, p.WKth,            p.WKtl);
    k_split_wt<<<dim3(4, 16), dim3(32, 8)>>>(WKc, p.WKth + KD*DM,    p.WKtl + KD*DM);

    // ---- encoder: 2x self-attn layers on train_feat (x lives in g_mem) ----
    k_trans_in<<<dim3(32, 16, BATCH), dim3(32, 8)>>>(train, p.mem, p.Xh, p.Xl);
    self_block(p.mem, bKs, p);
    self_block(p.mem, bKs, p);

    // ---- cross-attn invariants (p.Xh/Xl currently hold memory's split) ----
    proj_l2(1, bKc, p.Wkmh, p.Wkml, p);                               // wk(memory)
    k_ew_mul_label<<<dim3(256, BATCH), 256>>>(p.mem, lbl, p.V2);      // memory*pos
    k_tsplit<<<dim3(32, 16, BATCH), dim3(32, 8)>>>(p.V2, p.V2th, p.V2tl);

    // ---- decoders ----
    run_decoder(train, out,                        bKs, bKc, lbl, p);
    run_decoder(test,  out + (size_t)BATCH*DM*SEQ, bKs, bKc, lbl, p);
}

// round 6
// speedup vs baseline: 2.4501x; 1.0950x over previous
#include <cuda_runtime.h>
#include <cuda_bf16.h>
#include <math.h>
#include <stdint.h>

#define BATCH 16
#define SEQ   1024
#define DM    512
#define KD    128
#define TEMP_F 30.0f
#define EPB   (SEQ*DM)
#define NORM_SCALE_F 0.011048543456039806f   // sqrt(1/(512*16))

typedef __nv_bfloat16 bf16;

// ---------------- scratch (static device memory; allocation-free) ----------
__device__ __align__(16) float g_Sc  [BATCH*SEQ*SEQ];                        // fp32 scores
__device__ __align__(16) bf16 g_Xh  [BATCH*SEQ*DM], g_Xl  [BATCH*SEQ*DM];    // x   [B][S][D]
__device__ __align__(16) bf16 g_Xth [BATCH*SEQ*DM], g_Xtl [BATCH*SEQ*DM];    // x^T [B][D][S]
__device__ __align__(16) bf16 g_V2th[BATCH*SEQ*DM], g_V2tl[BATCH*SEQ*DM];    // (mem*lbl)^T
__device__ __align__(16) bf16 g_Bh  [BATCH*SEQ*DM], g_Bl  [BATCH*SEQ*DM];    // residual sums
__device__ __align__(16) bf16 g_Wh  [BATCH*SEQ*KD], g_Wl  [BATCH*SEQ*KD];
__device__ __align__(16) bf16 g_Wkmh[BATCH*SEQ*KD], g_Wkml[BATCH*SEQ*KD];
__device__ __align__(16) bf16 g_Sch [BATCH*SEQ*SEQ], g_Scl[BATCH*SEQ*SEQ];
__device__ __align__(16) bf16 g_WKth[2*KD*DM], g_WKtl[2*KD*DM];              // WK^T [K][D]
__device__ float g_mask[BATCH*SEQ];
__device__ float g_part[BATCH*32*3];
__device__ float g_ssf [BATCH];
__device__ float g_cab [BATCH*2];

__device__ __forceinline__ void bsplit(float x, bf16& h, bf16& l)
{
    bf16 hh = __float2bfloat16(x);
    h = hh;
    l = __float2bfloat16(x - __bfloat162float(hh));
}
__device__ __forceinline__ float upk0(uint32_t u){ return __bfloat162float(((__nv_bfloat162*)&u)->x); }
__device__ __forceinline__ float upk1(uint32_t u){ return __bfloat162float(((__nv_bfloat162*)&u)->y); }
__device__ __forceinline__ uint32_t pack2(bf16 a, bf16 b){
    __nv_bfloat162 t; t.x = a; t.y = b; return *(uint32_t*)&t;
}

// ====================== pure-bf16 3-pass tensor-core GEMM ==================
// C = (Ah+Al) @ (Bh+Bl)^T (drop Al*Bl).  A:[M,K], B:[N,K], both row-major.
// EPI: 0 = fp32 C store; 1 = bias + row-L2 + bf16 split (proj, N=128, grid.x=1)
//      2 = +residual x, emit splits, sumsq partials (self AV)
//      3 = +residual x, emit splits, Saa/Sab/Sbb partials (cross t3)

__device__ __forceinline__ void mma_bf16(float* c, const uint32_t* a, const uint32_t* b)
{
    asm volatile(
        "mma.sync.aligned.m16n8k16.row.col.f32.bf16.bf16.f32 "
        "{%0,%1,%2,%3},{%4,%5,%6,%7},{%8,%9},{%0,%1,%2,%3};"
        : "+f"(c[0]), "+f"(c[1]), "+f"(c[2]), "+f"(c[3])
        : "r"(a[0]), "r"(a[1]), "r"(a[2]), "r"(a[3]), "r"(b[0]), "r"(b[1]));
}

#define CP_ASYNC16(dst_u32, src_ptr) \
    asm volatile("cp.async.cg.shared.global [%0], [%1], 16;\n" :: "r"(dst_u32), "l"(src_ptr))
#define CP_COMMIT()  asm volatile("cp.async.commit_group;\n" ::)
#define CP_WAIT_1()  asm volatile("cp.async.wait_group 1;\n" ::)
#define CP_WAIT_0()  asm volatile("cp.async.wait_group 0;\n" ::)

#define TILE_W   2560
#define STAGE_W  (4*TILE_W)
#define GEMM_SMEM_BYTES (2*STAGE_W*4)

template<int EPI>
__global__ void __launch_bounds__(256, 2)
k_gemm(const bf16* __restrict__ Ahg, const bf16* __restrict__ Alg,
       const bf16* __restrict__ Bhg, const bf16* __restrict__ Blg,
       float* __restrict__ Cg, bf16* __restrict__ OH, bf16* __restrict__ OL,
       const bf16* __restrict__ RXh, const bf16* __restrict__ RXl,
       const float* __restrict__ bm_aux,   // EPI1: bias[N]; EPI3: mask[B*SEQ]
       float* __restrict__ part,
       int M, int N, int K, size_t sA, size_t sB, size_t sC)
{
    extern __shared__ uint32_t sm[];
    const bf16* Ah = Ahg + (size_t)blockIdx.z * sA;
    const bf16* Al = Alg + (size_t)blockIdx.z * sA;
    const bf16* Bh = Bhg + (size_t)blockIdx.z * sB;
    const bf16* Bl = Blg + (size_t)blockIdx.z * sB;

    const int bm = blockIdx.y * 128;
    const int bn = blockIdx.x * 128;
    const int tid  = threadIdx.x;
    const int lane = tid & 31;
    const int warp = tid >> 5;
    const int wm = (warp & 1) * 64;
    const int wn = (warp >> 1) * 32;
    const int qid = lane >> 2;
    const int tig = lane & 3;

    const uint32_t sbase = (uint32_t)__cvta_generic_to_shared(sm);

    auto load_stage = [&](int st, int k0) {
        uint32_t stb = sbase + st * (STAGE_W * 4);
        #pragma unroll
        for (int h = 0; h < 2; h++) {
            int idx = tid + h * 256;
            int rr = idx >> 2, cc = idx & 3;
            uint32_t woff = (rr * 20 + cc * 4) * 4;
            size_t ga = (size_t)(bm + rr) * K + k0 + cc * 8;
            size_t gb = (size_t)(bn + rr) * K + k0 + cc * 8;
            CP_ASYNC16(stb + 0*TILE_W*4 + woff, Ah + ga);
            CP_ASYNC16(stb + 1*TILE_W*4 + woff, Al + ga);
            CP_ASYNC16(stb + 2*TILE_W*4 + woff, Bh + gb);
            CP_ASYNC16(stb + 3*TILE_W*4 + woff, Bl + gb);
        }
        CP_COMMIT();
    };

    float acc[4][4][4] = {};
    const int nIter = K >> 5;
    load_stage(0, 0);

    for (int it = 0; it < nIter; ++it) {
        if (it + 1 < nIter) { load_stage((it + 1) & 1, (it + 1) * 32); CP_WAIT_1(); }
        else                { CP_WAIT_0(); }
        __syncthreads();

        const uint32_t* As_h = sm + (it & 1) * STAGE_W;
        const uint32_t* As_l = As_h + TILE_W;
        const uint32_t* Bs_h = As_h + 2*TILE_W;
        const uint32_t* Bs_l = As_h + 3*TILE_W;

        #pragma unroll
        for (int ks = 0; ks < 2; ks++) {
            const int kw = ks * 8 + tig;
            uint32_t ah[4][4], bh[4][2], bl[4][2];
            #pragma unroll
            for (int mi = 0; mi < 4; mi++) {
                int b0 = (wm + mi*16 + qid) * 20 + kw;
                ah[mi][0] = As_h[b0];       ah[mi][1] = As_h[b0 + 160];
                ah[mi][2] = As_h[b0 + 4];   ah[mi][3] = As_h[b0 + 164];
            }
            #pragma unroll
            for (int ni = 0; ni < 4; ni++) {
                int b0 = (wn + ni*8 + qid) * 20 + kw;
                bh[ni][0] = Bs_h[b0];  bh[ni][1] = Bs_h[b0 + 4];
                bl[ni][0] = Bs_l[b0];  bl[ni][1] = Bs_l[b0 + 4];
            }
            #pragma unroll
            for (int mi = 0; mi < 4; mi++)
                #pragma unroll
                for (int ni = 0; ni < 4; ni++)
                    mma_bf16(acc[mi][ni], ah[mi], bh[ni]);
            #pragma unroll
            for (int mi = 0; mi < 4; mi++)
                #pragma unroll
                for (int ni = 0; ni < 4; ni++)
                    mma_bf16(acc[mi][ni], ah[mi], bl[ni]);
            uint32_t al[4][4];
            #pragma unroll
            for (int mi = 0; mi < 4; mi++) {
                int b0 = (wm + mi*16 + qid) * 20 + kw;
                al[mi][0] = As_l[b0];       al[mi][1] = As_l[b0 + 160];
                al[mi][2] = As_l[b0 + 4];   al[mi][3] = As_l[b0 + 164];
            }
            #pragma unroll
            for (int mi = 0; mi < 4; mi++)
                #pragma unroll
                for (int ni = 0; ni < 4; ni++)
                    mma_bf16(acc[mi][ni], al[mi], bh[ni]);
        }
        __syncthreads();
    }

    const size_t zC = (size_t)blockIdx.z * sC;

    if (EPI == 0) {
        float* C = Cg + zC;
        #pragma unroll
        for (int mi = 0; mi < 4; mi++)
            #pragma unroll
            for (int ni = 0; ni < 4; ni++) {
                const int r = bm + wm + mi * 16 + qid;
                const int c = bn + wn + ni * 8 + 2 * tig;
                *(float2*)&C[(size_t)r * N + c]       = make_float2(acc[mi][ni][0], acc[mi][ni][1]);
                *(float2*)&C[(size_t)(r + 8) * N + c] = make_float2(acc[mi][ni][2], acc[mi][ni][3]);
            }
    }
    else if (EPI == 1) {
        // bias + row-wise L2 normalize over N=128, emit bf16 splits
        float* srow = (float*)sm;   // [128][4]
        float rs[4][2];
        #pragma unroll
        for (int mi = 0; mi < 4; mi++) { rs[mi][0] = 0.f; rs[mi][1] = 0.f; }
        #pragma unroll
        for (int mi = 0; mi < 4; mi++)
            #pragma unroll
            for (int ni = 0; ni < 4; ni++) {
                const int c = bn + wn + ni * 8 + 2 * tig;
                float b0 = bm_aux[c], b1 = bm_aux[c + 1];
                acc[mi][ni][0] += b0; acc[mi][ni][1] += b1;
                acc[mi][ni][2] += b0; acc[mi][ni][3] += b1;
                rs[mi][0] += acc[mi][ni][0]*acc[mi][ni][0] + acc[mi][ni][1]*acc[mi][ni][1];
                rs[mi][1] += acc[mi][ni][2]*acc[mi][ni][2] + acc[mi][ni][3]*acc[mi][ni][3];
            }
        #pragma unroll
        for (int mi = 0; mi < 4; mi++)
            #pragma unroll
            for (int h = 0; h < 2; h++) {
                float v = rs[mi][h];
                v += __shfl_xor_sync(0xffffffffu, v, 1);
                v += __shfl_xor_sync(0xffffffffu, v, 2);
                rs[mi][h] = v;
            }
        if (tig == 0)
            #pragma unroll
            for (int mi = 0; mi < 4; mi++)
                #pragma unroll
                for (int h = 0; h < 2; h++)
                    srow[(wm + mi*16 + qid + h*8) * 4 + (wn >> 5)] = rs[mi][h];
        __syncthreads();
        #pragma unroll
        for (int mi = 0; mi < 4; mi++)
            #pragma unroll
            for (int h = 0; h < 2; h++) {
                int rl = wm + mi*16 + qid + h*8;
                float tot = srow[rl*4] + srow[rl*4+1] + srow[rl*4+2] + srow[rl*4+3];
                float inv = 1.f / fmaxf(sqrtf(tot), 1e-12f);
                #pragma unroll
                for (int ni = 0; ni < 4; ni++) {
                    const int c = bn + wn + ni * 8 + 2 * tig;
                    size_t i = zC + (size_t)(bm + rl) * N + c;
                    bf16 h0,l0,h1,l1;
                    bsplit(acc[mi][ni][2*h]   * inv, h0, l0);
                    bsplit(acc[mi][ni][2*h+1] * inv, h1, l1);
                    *(uint32_t*)(OH + i) = pack2(h0, h1);
                    *(uint32_t*)(OL + i) = pack2(l0, l1);
                }
            }
    }
    else {  // EPI 2 / 3: residual add + split emit + partial sums
        const bf16* Xh = RXh + zC;
        const bf16* Xl = RXl + zC;
        float saa = 0.f, sab = 0.f, sbb = 0.f;
        #pragma unroll
        for (int mi = 0; mi < 4; mi++) {
            const int r0 = bm + wm + mi * 16 + qid;
            float mk0 = 0.f, mk1 = 0.f;
            if (EPI == 3) {
                mk0 = bm_aux[blockIdx.z * SEQ + r0];
                mk1 = bm_aux[blockIdx.z * SEQ + r0 + 8];
            }
            #pragma unroll
            for (int ni = 0; ni < 4; ni++) {
                const int c = bn + wn + ni * 8 + 2 * tig;
                size_t i0 = (size_t)r0 * N + c;
                size_t i1 = i0 + (size_t)8 * N;
                uint32_t xh0 = *(const uint32_t*)(Xh + i0), xl0 = *(const uint32_t*)(Xl + i0);
                uint32_t xh1 = *(const uint32_t*)(Xh + i1), xl1 = *(const uint32_t*)(Xl + i1);
                float x00 = upk0(xh0)+upk0(xl0), x01 = upk1(xh0)+upk1(xl0);
                float x10 = upk0(xh1)+upk0(xl1), x11 = upk1(xh1)+upk1(xl1);
                float v00 = acc[mi][ni][0] + x00, v01 = acc[mi][ni][1] + x01;
                float v10 = acc[mi][ni][2] + x10, v11 = acc[mi][ni][3] + x11;
                sbb += v00*v00 + v01*v01 + v10*v10 + v11*v11;
                if (EPI == 3) {
                    float a00 = x00*mk0, a01 = x01*mk0, a10 = x10*mk1, a11 = x11*mk1;
                    saa += a00*a00 + a01*a01 + a10*a10 + a11*a11;
                    sab += a00*v00 + a01*v01 + a10*v10 + a11*v11;
                }
                bf16 h0,l0,h1,l1;
                bsplit(v00, h0, l0); bsplit(v01, h1, l1);
                *(uint32_t*)(OH + zC + i0) = pack2(h0, h1);
                *(uint32_t*)(OL + zC + i0) = pack2(l0, l1);
                bsplit(v10, h0, l0); bsplit(v11, h1, l1);
                *(uint32_t*)(OH + zC + i1) = pack2(h0, h1);
                *(uint32_t*)(OL + zC + i1) = pack2(l0, l1);
            }
        }
        // block reduce (deterministic): warp shfl, then smem
        float* red = (float*)sm;   // [3][8]
        #pragma unroll
        for (int o = 16; o; o >>= 1) {
            sbb += __shfl_xor_sync(0xffffffffu, sbb, o);
            if (EPI == 3) {
                saa += __shfl_xor_sync(0xffffffffu, saa, o);
                sab += __shfl_xor_sync(0xffffffffu, sab, o);
            }
        }
        if (lane == 0) {
            red[warp] = sbb;
            if (EPI == 3) { red[8 + warp] = saa; red[16 + warp] = sab; }
        }
        __syncthreads();
        if (tid == 0) {
            const int tileId = blockIdx.y * gridDim.x + blockIdx.x;   // 0..31
            float tb = 0.f; for (int i = 0; i < 8; i++) tb += red[i];
            part[blockIdx.z * 32 + tileId] = tb;
            if (EPI == 3) {
                float ta = 0.f, tc = 0.f;
                for (int i = 0; i < 8; i++) { ta += red[8+i]; tc += red[16+i]; }
                part[512 + blockIdx.z * 32 + tileId]  = ta;   // Saa
                part[1024 + blockIdx.z * 32 + tileId] = tc;   // Sab
            }
        }
    }
}

// ---------------- weight transpose + split: WK[D][K] -> WKt[K][D] ----------
__global__ void k_split_wt(const float* __restrict__ Wk, bf16* __restrict__ th,
                           bf16* __restrict__ tl)
{
    __shared__ float tile[32][33];
    int k0 = blockIdx.x * 32, d0 = blockIdx.y * 32;
    for (int r = threadIdx.y; r < 32; r += 8)
        tile[r][threadIdx.x] = Wk[(size_t)(d0 + r) * KD + k0 + threadIdx.x];
    __syncthreads();
    for (int r = threadIdx.y; r < 32; r += 8) {
        size_t idx = (size_t)(k0 + r) * DM + d0 + threadIdx.x;
        bsplit(tile[threadIdx.x][r], th[idx], tl[idx]);
    }
}

// ---------------- input transpose: [B,D,S] fp32 -> splits [B,S,D] ----------
__global__ void k_trans_in(const float* __restrict__ in,
                           bf16* __restrict__ Xh, bf16* __restrict__ Xl)
{
    __shared__ float tile[32][33];
    int b = blockIdx.z;
    int d0 = blockIdx.y * 32, s0 = blockIdx.x * 32;
    for (int r = threadIdx.y; r < 32; r += 8)
        tile[r][threadIdx.x] = in[((size_t)b*DM + d0 + r) * SEQ + s0 + threadIdx.x];
    __syncthreads();
    for (int r = threadIdx.y; r < 32; r += 8) {
        size_t idx = ((size_t)b*SEQ + s0 + r) * DM + d0 + threadIdx.x;
        bsplit(tile[threadIdx.x][r], Xh[idx], Xl[idx]);
    }
}

// ---------------- output transpose: splits [B,S,D] -> fp32 [B,D,S] ---------
__global__ void k_trans_out(const bf16* __restrict__ Xh, const bf16* __restrict__ Xl,
                            float* __restrict__ out)
{
    __shared__ float tile[32][33];
    int b = blockIdx.z;
    int d0 = blockIdx.y * 32, s0 = blockIdx.x * 32;
    for (int r = threadIdx.y; r < 32; r += 8) {
        size_t idx = ((size_t)b*SEQ + s0 + r) * DM + d0 + threadIdx.x;
        tile[r][threadIdx.x] = __bfloat162float(Xh[idx]) + __bfloat162float(Xl[idx]);
    }
    __syncthreads();
    for (int r = threadIdx.y; r < 32; r += 8)
        out[((size_t)b*DM + d0 + r) * SEQ + s0 + threadIdx.x] = tile[threadIdx.x][r];
}

// ---------------- split transpose: [B,S,D] -> [B,D,S] (h/l preserved) ------
__global__ void k_tsplit(const bf16* __restrict__ Xh, const bf16* __restrict__ Xl,
                         bf16* __restrict__ th, bf16* __restrict__ tl)
{
    __shared__ bf16 tH[32][33], tL[32][33];
    int b = blockIdx.z;
    int s0 = blockIdx.x * 32, d0 = blockIdx.y * 32;
    for (int r = threadIdx.y; r < 32; r += 8) {
        size_t idx = ((size_t)b*SEQ + s0 + r) * DM + d0 + threadIdx.x;
        tH[r][threadIdx.x] = Xh[idx];
        tL[r][threadIdx.x] = Xl[idx];
    }
    __syncthreads();
    for (int r = threadIdx.y; r < 32; r += 8) {
        size_t idx = ((size_t)b*DM + d0 + r) * SEQ + s0 + threadIdx.x;
        th[idx] = tH[threadIdx.x][r];
        tl[idx] = tL[threadIdx.x][r];
    }
}

// ---------------- V2^T: (mem * label) transposed + split --------------------
__global__ void k_v2t(const bf16* __restrict__ Mh, const bf16* __restrict__ Ml,
                      const float* __restrict__ lbl,
                      bf16* __restrict__ th, bf16* __restrict__ tl)
{
    __shared__ float tile[32][33];
    int b = blockIdx.z;
    int s0 = blockIdx.x * 32, d0 = blockIdx.y * 32;
    float L = lbl[b*SEQ + s0 + threadIdx.y];   // placeholder; real per-row below
    (void)L;
    for (int r = threadIdx.y; r < 32; r += 8) {
        size_t idx = ((size_t)b*SEQ + s0 + r) * DM + d0 + threadIdx.x;
        float v = __bfloat162float(Mh[idx]) + __bfloat162float(Ml[idx]);
        tile[r][threadIdx.x] = v * lbl[b*SEQ + s0 + r];
    }
    __syncthreads();
    for (int r = threadIdx.y; r < 32; r += 8) {
        size_t idx = ((size_t)b*DM + d0 + r) * SEQ + s0 + threadIdx.x;
        bsplit(tile[threadIdx.x][r], th[idx], tl[idx]);
    }
}

// ---------------- softmax (optionally fused mask GEMV) ----------------------
template<bool MASK>
__global__ void k_softmax(const float* __restrict__ Sc, bf16* __restrict__ Ph,
                          bf16* __restrict__ Pl, float* __restrict__ mask,
                          const float* __restrict__ lbl)
{
    __shared__ float sh1[8], sh2[8];
    int b = blockIdx.y, q = blockIdx.x, t = threadIdx.x;   // 256 threads
    size_t ro = ((size_t)b*SEQ + q) * SEQ;
    float4 v = reinterpret_cast<const float4*>(Sc + ro)[t];
    v.x *= TEMP_F; v.y *= TEMP_F; v.z *= TEMP_F; v.w *= TEMP_F;
    float m = fmaxf(fmaxf(v.x, v.y), fmaxf(v.z, v.w));
    #pragma unroll
    for (int o = 16; o; o >>= 1) m = fmaxf(m, __shfl_xor_sync(0xffffffffu, m, o));
    if ((t & 31) == 0) sh1[t >> 5] = m;
    __syncthreads();
    m = fmaxf(fmaxf(fmaxf(sh1[0], sh1[1]), fmaxf(sh1[2], sh1[3])),
              fmaxf(fmaxf(sh1[4], sh1[5]), fmaxf(sh1[6], sh1[7])));
    v.x = __expf(v.x - m); v.y = __expf(v.y - m);
    v.z = __expf(v.z - m); v.w = __expf(v.w - m);
    float sum = v.x + v.y + v.z + v.w;
    #pragma unroll
    for (int o = 16; o; o >>= 1) sum += __shfl_xor_sync(0xffffffffu, sum, o);
    if ((t & 31) == 0) sh2[t >> 5] = sum;
    __syncthreads();
    sum = sh2[0]+sh2[1]+sh2[2]+sh2[3]+sh2[4]+sh2[5]+sh2[6]+sh2[7];
    float inv = 1.f / sum;
    float p0 = v.x*inv, p1 = v.y*inv, p2 = v.z*inv, p3 = v.w*inv;
    bf16 h0,l0,h1,l1,h2,l2,h3,l3;
    bsplit(p0,h0,l0); bsplit(p1,h1,l1); bsplit(p2,h2,l2); bsplit(p3,h3,l3);
    uint2 uh; uh.x = pack2(h0,h1); uh.y = pack2(h2,h3);
    uint2 ul; ul.x = pack2(l0,l1); ul.y = pack2(l2,l3);
    *(uint2*)(Ph + ro + 4*t) = uh;
    *(uint2*)(Pl + ro + 4*t) = ul;
    if (MASK) {
        float4 L = reinterpret_cast<const float4*>(lbl + (size_t)b*SEQ)[t];
        float s = p0*L.x + p1*L.y + p2*L.z + p3*L.w;
        #pragma unroll
        for (int o = 16; o; o >>= 1) s += __shfl_xor_sync(0xffffffffu, s, o);
        __syncthreads();
        if ((t & 31) == 0) sh1[t >> 5] = s;
        __syncthreads();
        if (t == 0)
            mask[b*SEQ + q] = sh1[0]+sh1[1]+sh1[2]+sh1[3]+sh1[4]+sh1[5]+sh1[6]+sh1[7];
    }
}

// ---------------- scalar-factor kernels ------------------------------------
__global__ void k_ssfinal32(const float* __restrict__ part, float* __restrict__ ssf)
{
    int b = blockIdx.x;
    float v = part[b*32 + threadIdx.x];
    #pragma unroll
    for (int o = 16; o; o >>= 1) v += __shfl_xor_sync(0xffffffffu, v, o);
    if (threadIdx.x == 0)
        ssf[b] = NORM_SCALE_F * sqrtf(524288.f / (v + 1e-5f));
}

__global__ void k_cross_factors(const float* __restrict__ part, float* __restrict__ cab)
{
    int b = blockIdx.x;
    float sbb = part[b*32 + threadIdx.x];
    float saa = part[512 + b*32 + threadIdx.x];
    float sab = part[1024 + b*32 + threadIdx.x];
    #pragma unroll
    for (int o = 16; o; o >>= 1) {
        sbb += __shfl_xor_sync(0xffffffffu, sbb, o);
        saa += __shfl_xor_sync(0xffffffffu, saa, o);
        sab += __shfl_xor_sync(0xffffffffu, sab, o);
    }
    if (threadIdx.x == 0) {
        float f2 = NORM_SCALE_F * sqrtf(524288.f / (saa + 1e-5f));
        float f4 = NORM_SCALE_F * sqrtf(524288.f / (sbb + 1e-5f));
        float sf = f2*f2*saa + 2.f*f2*f4*sab + f4*f4*sbb;
        float F  = NORM_SCALE_F * sqrtf(524288.f / (sf + 1e-5f));
        cab[b*2]   = F * f2;
        cab[b*2+1] = F * f4;
    }
}

// ---------------- vectorized scale / final passes (8 elems/thread) ---------
__global__ void k_scale_emit8(const bf16* __restrict__ Bh, const bf16* __restrict__ Bl,
                              const float* __restrict__ ssf,
                              bf16* __restrict__ Xh, bf16* __restrict__ Xl)
{
    int b = blockIdx.y;
    float f = ssf[b];
    size_t i = (size_t)b*EPB + (size_t)blockIdx.x*2048 + threadIdx.x*8;
    uint4 uh = *(const uint4*)(Bh + i);
    uint4 ul = *(const uint4*)(Bl + i);
    uint32_t oh[4], ol[4];
    const uint32_t* ph = (const uint32_t*)&uh;
    const uint32_t* pl = (const uint32_t*)&ul;
    #pragma unroll
    for (int j = 0; j < 4; j++) {
        float v0 = (upk0(ph[j]) + upk0(pl[j])) * f;
        float v1 = (upk1(ph[j]) + upk1(pl[j])) * f;
        bf16 h0,l0,h1,l1;
        bsplit(v0,h0,l0); bsplit(v1,h1,l1);
        oh[j] = pack2(h0,h1); ol[j] = pack2(l0,l1);
    }
    *(uint4*)(Xh + i) = *(uint4*)oh;
    *(uint4*)(Xl + i) = *(uint4*)ol;
}

__global__ void k_cross_final8(bf16* __restrict__ Xh, bf16* __restrict__ Xl,
                               const bf16* __restrict__ Bh, const bf16* __restrict__ Bl,
                               const float* __restrict__ mask,
                               const float* __restrict__ cab)
{
    int b = blockIdx.y;
    float ca = cab[b*2], cb = cab[b*2+1];
    size_t e = (size_t)blockIdx.x*2048 + threadIdx.x*8;
    float mk = mask[b*SEQ + (int)(e >> 9)];
    size_t i = (size_t)b*EPB + e;
    uint4 xh = *(const uint4*)(Xh + i);
    uint4 xl = *(const uint4*)(Xl + i);
    uint4 vh = *(const uint4*)(Bh + i);
    uint4 vl = *(const uint4*)(Bl + i);
    uint32_t oh[4], ol[4];
    const uint32_t* pxh = (const uint32_t*)&xh;
    const uint32_t* pxl = (const uint32_t*)&xl;
    const uint32_t* pvh = (const uint32_t*)&vh;
    const uint32_t* pvl = (const uint32_t*)&vl;
    float camk = ca * mk;
    #pragma unroll
    for (int j = 0; j < 4; j++) {
        float x0 = upk0(pxh[j]) + upk0(pxl[j]);
        float x1 = upk1(pxh[j]) + upk1(pxl[j]);
        float b0 = upk0(pvh[j]) + upk0(pvl[j]);
        float b1 = upk1(pvh[j]) + upk1(pvl[j]);
        float v0 = camk * x0 + cb * b0;
        float v1 = camk * x1 + cb * b1;
        bf16 h0,l0,h1,l1;
        bsplit(v0,h0,l0); bsplit(v1,h1,l1);
        oh[j] = pack2(h0,h1); ol[j] = pack2(l0,l1);
    }
    *(uint4*)(Xh + i) = *(uint4*)oh;
    *(uint4*)(Xl + i) = *(uint4*)ol;
}

// =================== host-side orchestration ===============================
namespace {

struct Ptrs {
    float *Sc, *mask, *part, *ssf, *cab;
    bf16 *Xh, *Xl, *Xth, *Xtl, *V2th, *V2tl, *Bh, *Bl,
         *Wh, *Wl, *Wkmh, *Wkml, *Sch, *Scl, *WKth, *WKtl;
};

inline void proj(int wsel, const float* bK, bf16* outH, bf16* outL, const Ptrs& p)
{
    k_gemm<1><<<dim3(1, 8, BATCH), 256, GEMM_SMEM_BYTES>>>(
        p.Xh, p.Xl, p.WKth + (size_t)wsel*KD*DM, p.WKtl + (size_t)wsel*KD*DM,
        nullptr, outH, outL, nullptr, nullptr, bK, nullptr,
        SEQ, KD, DM, (size_t)SEQ*DM, 0, (size_t)SEQ*KD);
}

inline void self_block(const float* bKs, const Ptrs& p)
{
    k_tsplit<<<dim3(32, 16, BATCH), dim3(32, 8)>>>(p.Xh, p.Xl, p.Xth, p.Xtl);
    proj(0, bKs, p.Wh, p.Wl, p);
    k_gemm<0><<<dim3(8, 8, BATCH), 256, GEMM_SMEM_BYTES>>>(
        p.Wh, p.Wl, p.Wh, p.Wl, p.Sc, nullptr, nullptr, nullptr, nullptr,
        nullptr, nullptr, SEQ, SEQ, KD, (size_t)SEQ*KD, (size_t)SEQ*KD, (size_t)SEQ*SEQ);
    k_softmax<false><<<dim3(SEQ, BATCH), 256>>>(p.Sc, p.Sch, p.Scl, nullptr, nullptr);
    k_gemm<2><<<dim3(4, 8, BATCH), 256, GEMM_SMEM_BYTES>>>(
        p.Sch, p.Scl, p.Xth, p.Xtl, nullptr, p.Bh, p.Bl, p.Xh, p.Xl,
        nullptr, p.part, SEQ, DM, SEQ, (size_t)SEQ*SEQ, (size_t)DM*SEQ, (size_t)SEQ*DM);
    k_ssfinal32<<<BATCH, 32>>>(p.part, p.ssf);
    k_scale_emit8<<<dim3(256, BATCH), 256>>>(p.Bh, p.Bl, p.ssf, p.Xh, p.Xl);
}

inline void cross_block(const float* bKc, const float* lbl, const Ptrs& p)
{
    proj(1, bKc, p.Wh, p.Wl, p);
    k_gemm<0><<<dim3(8, 8, BATCH), 256, GEMM_SMEM_BYTES>>>(
        p.Wh, p.Wl, p.Wkmh, p.Wkml, p.Sc, nullptr, nullptr, nullptr, nullptr,
        nullptr, nullptr, SEQ, SEQ, KD, (size_t)SEQ*KD, (size_t)SEQ*KD, (size_t)SEQ*SEQ);
    k_softmax<true><<<dim3(SEQ, BATCH), 256>>>(p.Sc, p.Sch, p.Scl, p.mask, lbl);
    k_gemm<3><<<dim3(4, 8, BATCH), 256, GEMM_SMEM_BYTES>>>(
        p.Sch, p.Scl, p.V2th, p.V2tl, nullptr, p.Bh, p.Bl, p.Xh, p.Xl,
        p.mask, p.part, SEQ, DM, SEQ, (size_t)SEQ*SEQ, (size_t)DM*SEQ, (size_t)SEQ*DM);
    k_cross_factors<<<BATCH, 32>>>(p.part, p.cab);
    k_cross_final8<<<dim3(256, BATCH), 256>>>(p.Xh, p.Xl, p.Bh, p.Bl, p.mask, p.cab);
}

inline void run_decoder(const float* src, float* outp, const float* bKs,
                        const float* bKc, const float* lbl, const Ptrs& p)
{
    k_trans_in<<<dim3(32, 16, BATCH), dim3(32, 8)>>>(src, p.Xh, p.Xl);
    for (int l = 0; l < 2; l++) {
        self_block(bKs, p);
        cross_block(bKc, lbl, p);
    }
    k_trans_out<<<dim3(32, 16, BATCH), dim3(32, 8)>>>(p.Xh, p.Xl, outp);
}

} // namespace

extern "C" void kernel_launch(void* const* d_in, const int* in_sizes, int n_in,
                              void* d_out, int out_size)
{
    const float* train = (const float*)d_in[0];
    const float* test  = (const float*)d_in[1];
    const float* lbl   = (const float*)d_in[2];
    const float* WKs   = (const float*)d_in[3];
    const float* bKs   = (const float*)d_in[4];
    const float* WKc   = (const float*)d_in[5];
    const float* bKc   = (const float*)d_in[6];
    float* out = (float*)d_out;

    cudaFuncSetAttribute(k_gemm<0>, cudaFuncAttributeMaxDynamicSharedMemorySize, GEMM_SMEM_BYTES);
    cudaFuncSetAttribute(k_gemm<1>, cudaFuncAttributeMaxDynamicSharedMemorySize, GEMM_SMEM_BYTES);
    cudaFuncSetAttribute(k_gemm<2>, cudaFuncAttributeMaxDynamicSharedMemorySize, GEMM_SMEM_BYTES);
    cudaFuncSetAttribute(k_gemm<3>, cudaFuncAttributeMaxDynamicSharedMemorySize, GEMM_SMEM_BYTES);

    Ptrs p;
    cudaGetSymbolAddress((void**)&p.Sc,   g_Sc);
    cudaGetSymbolAddress((void**)&p.mask, g_mask);
    cudaGetSymbolAddress((void**)&p.part, g_part);
    cudaGetSymbolAddress((void**)&p.ssf,  g_ssf);
    cudaGetSymbolAddress((void**)&p.cab,  g_cab);
    cudaGetSymbolAddress((void**)&p.Xh,   g_Xh);
    cudaGetSymbolAddress((void**)&p.Xl,   g_Xl);
    cudaGetSymbolAddress((void**)&p.Xth,  g_Xth);
    cudaGetSymbolAddress((void**)&p.Xtl,  g_Xtl);
    cudaGetSymbolAddress((void**)&p.V2th, g_V2th);
    cudaGetSymbolAddress((void**)&p.V2tl, g_V2tl);
    cudaGetSymbolAddress((void**)&p.Bh,   g_Bh);
    cudaGetSymbolAddress((void**)&p.Bl,   g_Bl);
    cudaGetSymbolAddress((void**)&p.Wh,   g_Wh);
    cudaGetSymbolAddress((void**)&p.Wl,   g_Wl);
    cudaGetSymbolAddress((void**)&p.Wkmh, g_Wkmh);
    cudaGetSymbolAddress((void**)&p.Wkml, g_Wkml);
    cudaGetSymbolAddress((void**)&p.Sch,  g_Sch);
    cudaGetSymbolAddress((void**)&p.Scl,  g_Scl);
    cudaGetSymbolAddress((void**)&p.WKth, g_WKth);
    cudaGetSymbolAddress((void**)&p.WKtl, g_WKtl);

    // weight transpose + split
    k_split_wt<<<dim3(4, 16), dim3(32, 8)>>>(WKs, p.WKth,         p.WKtl);
    k_split_wt<<<dim3(4, 16), dim3(32, 8)>>>(WKc, p.WKth + KD*DM, p.WKtl + KD*DM);

    // encoder: 2x self-attn on train_feat; result (memory) lives in Xh/Xl
    k_trans_in<<<dim3(32, 16, BATCH), dim3(32, 8)>>>(train, p.Xh, p.Xl);
    self_block(bKs, p);
    self_block(bKs, p);

    // cross-attn invariants from memory (while Xh/Xl still hold it)
    proj(1, bKc, p.Wkmh, p.Wkml, p);                                   // wk(memory)
    k_v2t<<<dim3(32, 16, BATCH), dim3(32, 8)>>>(p.Xh, p.Xl, lbl, p.V2th, p.V2tl);

    // decoders
    run_decoder(train, out,                        bKs, bKc, lbl, p);
    run_decoder(test,  out + (size_t)BATCH*DM*SEQ, bKs, bKc, lbl, p);
}